// round 1
// baseline (speedup 1.0000x reference)
#include <cuda_runtime.h>
#include <cuda_bf16.h>
#include <cstdint>

// Problem constants
#define Bq   2
#define Sq   4096
#define Dq   768
#define Hq   12
#define DKq  64
#define Mrows (Bq*Sq)        // 8192

// Scratch (device globals: allocation-free rule)
__device__ float g_q[(size_t)Bq*Hq*Sq*DKq];   // [B,H,S,DK]
__device__ float g_k[(size_t)Bq*Hq*Sq*DKq];
__device__ float g_v[(size_t)Bq*Hq*Sq*DKq];
__device__ float g_o[(size_t)Bq*Sq*Dq];       // [B,S,D]

// ---------------------------------------------------------------------------
// GEMM: C = A @ W^T + bias.  A:[M,768], W:[N,768] row-major, M=8192, N=768.
// Tile 128x64x16, 256 threads, 8x4 per thread.
// split==1: scatter output to [B,H,S,DK] layout. split==0: flat [M,N].
// ---------------------------------------------------------------------------
__global__ __launch_bounds__(256) void gemm_bias_kernel(
    const float* __restrict__ A, const float* __restrict__ W,
    const float* __restrict__ bias, float* __restrict__ C, int split)
{
    __shared__ float As[16][132];
    __shared__ float Ws[16][68];

    const int tid = threadIdx.x;
    const int tx = tid & 15;
    const int ty = tid >> 4;
    const int m0 = blockIdx.y * 128;
    const int n0 = blockIdx.x * 64;

    float acc[8][4];
#pragma unroll
    for (int i = 0; i < 8; i++)
#pragma unroll
        for (int j = 0; j < 4; j++) acc[i][j] = 0.f;

    for (int k0 = 0; k0 < 768; k0 += 16) {
        // Load A tile 128x16, transposed into As[k][m]
#pragma unroll
        for (int i = tid; i < 128 * 16; i += 256) {
            int m = i >> 4, k = i & 15;
            As[k][m] = A[(size_t)(m0 + m) * 768 + k0 + k];
        }
        // Load W tile 64x16 into Ws[k][n]
#pragma unroll
        for (int i = tid; i < 64 * 16; i += 256) {
            int n = i >> 4, k = i & 15;
            Ws[k][n] = W[(size_t)(n0 + n) * 768 + k0 + k];
        }
        __syncthreads();

#pragma unroll
        for (int kk = 0; kk < 16; kk++) {
            float4 a0 = *(const float4*)&As[kk][ty * 8];
            float4 a1 = *(const float4*)&As[kk][ty * 8 + 4];
            float4 w0 = *(const float4*)&Ws[kk][tx * 4];
            float a[8] = {a0.x, a0.y, a0.z, a0.w, a1.x, a1.y, a1.z, a1.w};
            float w[4] = {w0.x, w0.y, w0.z, w0.w};
#pragma unroll
            for (int i = 0; i < 8; i++)
#pragma unroll
                for (int j = 0; j < 4; j++) acc[i][j] += a[i] * w[j];
        }
        __syncthreads();
    }

#pragma unroll
    for (int i = 0; i < 8; i++) {
        int m = m0 + ty * 8 + i;
#pragma unroll
        for (int j = 0; j < 4; j++) {
            int n = n0 + tx * 4 + j;
            float v = acc[i][j] + bias[n];
            if (split) {
                int bb = m >> 12;        // m / 4096
                int ss = m & 4095;
                int hh = n >> 6;         // n / 64
                int dk = n & 63;
                C[(((size_t)bb * Hq + hh) * Sq + ss) * DKq + dk] = v;
            } else {
                C[(size_t)m * 768 + n] = v;
            }
        }
    }
}

// ---------------------------------------------------------------------------
// Flash attention, fp32. One block = 64 query rows for one (b,h).
// 256 threads: thread (r=tid/4, c=tid%4) owns row r and 16-wide column slice c.
// Online softmax; P staged through smem for the PV product.
// smem: Qs[64][68] + KsT[64][68] + Vs[64][68] + Ps[64][68] = 69632 B (dynamic)
// ---------------------------------------------------------------------------
#define TSTR 68
__global__ __launch_bounds__(256) void attn_kernel(
    const int* __restrict__ mask,
    const float* __restrict__ Q, const float* __restrict__ K,
    const float* __restrict__ V, float* __restrict__ O)
{
    extern __shared__ float smf[];
    float* Qs  = smf;
    float* KsT = smf + 64 * TSTR;
    float* Vs  = smf + 2 * 64 * TSTR;
    float* Ps  = smf + 3 * 64 * TSTR;

    const int qt = blockIdx.x;
    const int h  = blockIdx.y;
    const int b  = blockIdx.z;
    const int tid = threadIdx.x;
    const int r = tid >> 2;
    const int c = tid & 3;

    const size_t bh = (size_t)b * Hq + h;
    const float* Qb = Q + (bh * Sq + (size_t)qt * 64) * DKq;
    const float* Kb = K + bh * Sq * DKq;
    const float* Vb = V + bh * Sq * DKq;

    // Load Q tile (row-major, stride TSTR)
    for (int i = tid; i < 64 * 64; i += 256) {
        int rr = i >> 6, cc = i & 63;
        Qs[rr * TSTR + cc] = Qb[i];
    }

    float o[16];
#pragma unroll
    for (int j = 0; j < 16; j++) o[j] = 0.f;
    float mi = -1e30f, li = 0.f;

    const int qrow = qt * 64 + r;
    const int* mrowp = mask + ((size_t)b * Sq + qrow) * Sq;

    for (int kt = 0; kt < Sq / 64; kt++) {
        __syncthreads();   // previous PV done before overwriting tiles
        const float* Kt = Kb + (size_t)kt * 64 * DKq;
        const float* Vt = Vb + (size_t)kt * 64 * DKq;
        for (int i = tid; i < 64 * 64; i += 256) {
            int kv = i >> 6, k = i & 63;
            KsT[k * TSTR + kv] = Kt[i];  // transposed: KsT[k][kv]
            Vs[kv * TSTR + k]  = Vt[i];  // natural:    Vs[kv][d]
        }
        __syncthreads();

        // scores: s[j] = sum_k Qs[r][k] * K[c*16+j][k]
        float s[16];
#pragma unroll
        for (int j = 0; j < 16; j++) s[j] = 0.f;
        for (int k = 0; k < 64; k++) {
            float q = Qs[r * TSTR + k];
            const float4* kp4 = (const float4*)(KsT + k * TSTR + c * 16);
            float4 t0 = kp4[0], t1 = kp4[1], t2 = kp4[2], t3 = kp4[3];
            float kr[16] = {t0.x, t0.y, t0.z, t0.w, t1.x, t1.y, t1.z, t1.w,
                            t2.x, t2.y, t2.z, t2.w, t3.x, t3.y, t3.z, t3.w};
#pragma unroll
            for (int j = 0; j < 16; j++) s[j] += q * kr[j];
        }

        // scale + mask (replace with -1e9 where mask==0)
        const int4* mp = (const int4*)(mrowp + kt * 64 + c * 16);
        int4 ma = mp[0], mb = mp[1], mc = mp[2], md = mp[3];
        int mv[16] = {ma.x, ma.y, ma.z, ma.w, mb.x, mb.y, mb.z, mb.w,
                      mc.x, mc.y, mc.z, mc.w, md.x, md.y, md.z, md.w};
#pragma unroll
        for (int j = 0; j < 16; j++)
            s[j] = (mv[j] == 0) ? -1e9f : s[j] * 0.125f;

        // online softmax across the 4 lanes sharing row r
        float mloc = s[0];
#pragma unroll
        for (int j = 1; j < 16; j++) mloc = fmaxf(mloc, s[j]);
        mloc = fmaxf(mloc, __shfl_xor_sync(0xffffffffu, mloc, 1));
        mloc = fmaxf(mloc, __shfl_xor_sync(0xffffffffu, mloc, 2));
        float mnew = fmaxf(mi, mloc);

        float lloc = 0.f;
#pragma unroll
        for (int j = 0; j < 16; j++) {
            s[j] = __expf(s[j] - mnew);
            lloc += s[j];
        }
        lloc += __shfl_xor_sync(0xffffffffu, lloc, 1);
        lloc += __shfl_xor_sync(0xffffffffu, lloc, 2);

        float alpha = __expf(mi - mnew);
        li = li * alpha + lloc;
        mi = mnew;
#pragma unroll
        for (int j = 0; j < 16; j++) o[j] *= alpha;

        // stage P in smem
        float4* pp = (float4*)(Ps + r * TSTR + c * 16);
        pp[0] = make_float4(s[0], s[1], s[2], s[3]);
        pp[1] = make_float4(s[4], s[5], s[6], s[7]);
        pp[2] = make_float4(s[8], s[9], s[10], s[11]);
        pp[3] = make_float4(s[12], s[13], s[14], s[15]);
        __syncthreads();

        // PV: o[j] += sum_kv P[r][kv] * V[kv][c*16+j]
        for (int kv = 0; kv < 64; kv++) {
            float pv = Ps[r * TSTR + kv];
            const float4* vp4 = (const float4*)(Vs + kv * TSTR + c * 16);
            float4 v0 = vp4[0], v1 = vp4[1], v2 = vp4[2], v3 = vp4[3];
            float vr[16] = {v0.x, v0.y, v0.z, v0.w, v1.x, v1.y, v1.z, v1.w,
                            v2.x, v2.y, v2.z, v2.w, v3.x, v3.y, v3.z, v3.w};
#pragma unroll
            for (int j = 0; j < 16; j++) o[j] += pv * vr[j];
        }
    }

    const float inv = 1.0f / li;
    float* op = O + ((size_t)b * Sq + qrow) * Dq + h * DKq + c * 16;
#pragma unroll
    for (int j = 0; j < 16; j++) op[j] = o[j] * inv;
}

// ---------------------------------------------------------------------------
extern "C" void kernel_launch(void* const* d_in, const int* in_sizes, int n_in,
                              void* d_out, int out_size)
{
    const float* x    = (const float*)d_in[0];
    const int*   mask = (const int*)  d_in[1];
    const float* Wqp  = (const float*)d_in[2];
    const float* bqp  = (const float*)d_in[3];
    const float* Wkp  = (const float*)d_in[4];
    const float* bkp  = (const float*)d_in[5];
    const float* Wvp  = (const float*)d_in[6];
    const float* bvp  = (const float*)d_in[7];
    const float* Wop  = (const float*)d_in[8];
    const float* bop  = (const float*)d_in[9];
    float* out = (float*)d_out;

    float *qp, *kp, *vp, *op;
    cudaGetSymbolAddress((void**)&qp, g_q);
    cudaGetSymbolAddress((void**)&kp, g_k);
    cudaGetSymbolAddress((void**)&vp, g_v);
    cudaGetSymbolAddress((void**)&op, g_o);

    dim3 gg(768 / 64, Mrows / 128);   // (12, 64)

    gemm_bias_kernel<<<gg, 256>>>(x, Wqp, bqp, qp, 1);
    gemm_bias_kernel<<<gg, 256>>>(x, Wkp, bkp, kp, 1);
    gemm_bias_kernel<<<gg, 256>>>(x, Wvp, bvp, vp, 1);

    const int smem_bytes = 4 * 64 * TSTR * sizeof(float);  // 69632
    cudaFuncSetAttribute(attn_kernel,
                         cudaFuncAttributeMaxDynamicSharedMemorySize, smem_bytes);
    attn_kernel<<<dim3(Sq / 64, Hq, Bq), 256, smem_bytes>>>(mask, qp, kp, vp, op);

    gemm_bias_kernel<<<gg, 256>>>(op, Wop, bop, out, 0);
}

// round 2
// speedup vs baseline: 3.1195x; 3.1195x over previous
#include <cuda_runtime.h>
#include <cuda_bf16.h>
#include <cstdint>

// Problem constants
#define Bq   2
#define Sq   4096
#define Dq   768
#define Hq   12
#define DKq  64
#define Mrows (Bq*Sq)        // 8192

// Scratch (device globals: allocation-free rule)
__device__ float g_q[(size_t)Bq*Hq*Sq*DKq];   // [B,H,S,DK]
__device__ float g_k[(size_t)Bq*Hq*Sq*DKq];
__device__ float g_v[(size_t)Bq*Hq*Sq*DKq];
__device__ float g_o[(size_t)Bq*Sq*Dq];       // [B,S,D]

// ---------------------------------------------------------------------------
// GEMM: C = A @ W^T + bias.  A:[M,768], W:[N,768] row-major.
// Block tile 128x128, K-step 16, 256 threads, 8x8 per thread (split 4+4).
// split==1: scatter to [B,H,S,DK]; split==0: flat [M,768].
// ---------------------------------------------------------------------------
__global__ __launch_bounds__(256) void gemm_bias_kernel(
    const float* __restrict__ A, const float* __restrict__ W,
    const float* __restrict__ bias, float* __restrict__ C, int split)
{
    __shared__ float AsT[16][132];   // [k][m]
    __shared__ float WsT[16][132];   // [k][n]

    const int tid = threadIdx.x;
    const int tr = tid >> 4;         // 0..15
    const int tc = tid & 15;         // 0..15
    const int m0 = blockIdx.y * 128;
    const int n0 = blockIdx.x * 128;

    const int r0 = tr * 4, r1 = 64 + tr * 4;
    const int c0 = tc * 4, c1 = 64 + tc * 4;

    float acc[8][8];
#pragma unroll
    for (int i = 0; i < 8; i++)
#pragma unroll
        for (int j = 0; j < 8; j++) acc[i][j] = 0.f;

    for (int k0 = 0; k0 < 768; k0 += 16) {
        const float4* A4 = (const float4*)(A + (size_t)m0 * 768 + k0);
        const float4* W4 = (const float4*)(W + (size_t)n0 * 768 + k0);
#pragma unroll
        for (int i = tid; i < 512; i += 256) {
            int mm = i >> 2;
            int kq = (i & 3) << 2;
            float4 t = A4[(size_t)mm * 192 + (i & 3)];
            AsT[kq + 0][mm] = t.x;
            AsT[kq + 1][mm] = t.y;
            AsT[kq + 2][mm] = t.z;
            AsT[kq + 3][mm] = t.w;
        }
#pragma unroll
        for (int i = tid; i < 512; i += 256) {
            int nn = i >> 2;
            int kq = (i & 3) << 2;
            float4 t = W4[(size_t)nn * 192 + (i & 3)];
            WsT[kq + 0][nn] = t.x;
            WsT[kq + 1][nn] = t.y;
            WsT[kq + 2][nn] = t.z;
            WsT[kq + 3][nn] = t.w;
        }
        __syncthreads();

#pragma unroll
        for (int kk = 0; kk < 16; kk++) {
            float4 a0 = *(const float4*)&AsT[kk][r0];
            float4 a1 = *(const float4*)&AsT[kk][r1];
            float4 w0 = *(const float4*)&WsT[kk][c0];
            float4 w1 = *(const float4*)&WsT[kk][c1];
            float a[8] = {a0.x, a0.y, a0.z, a0.w, a1.x, a1.y, a1.z, a1.w};
            float w[8] = {w0.x, w0.y, w0.z, w0.w, w1.x, w1.y, w1.z, w1.w};
#pragma unroll
            for (int i = 0; i < 8; i++)
#pragma unroll
                for (int j = 0; j < 8; j++) acc[i][j] += a[i] * w[j];
        }
        __syncthreads();
    }

    float4 b0 = *(const float4*)&bias[n0 + c0];
    float4 b1 = *(const float4*)&bias[n0 + c1];

    const int h0 = (n0 + c0) >> 6, dk0 = (n0 + c0) & 63;
    const int h1 = (n0 + c1) >> 6, dk1 = (n0 + c1) & 63;

#pragma unroll
    for (int i = 0; i < 8; i++) {
        int m = m0 + ((i < 4) ? (r0 + i) : (r1 + i - 4));
        float4 v0 = make_float4(acc[i][0] + b0.x, acc[i][1] + b0.y,
                                acc[i][2] + b0.z, acc[i][3] + b0.w);
        float4 v1 = make_float4(acc[i][4] + b1.x, acc[i][5] + b1.y,
                                acc[i][6] + b1.z, acc[i][7] + b1.w);
        if (split) {
            int bb = m >> 12;
            int ss = m & 4095;
            *(float4*)&C[(((size_t)bb * Hq + h0) * Sq + ss) * DKq + dk0] = v0;
            *(float4*)&C[(((size_t)bb * Hq + h1) * Sq + ss) * DKq + dk1] = v1;
        } else {
            *(float4*)&C[(size_t)m * 768 + n0 + c0] = v0;
            *(float4*)&C[(size_t)m * 768 + n0 + c1] = v1;
        }
    }
}

// ---------------------------------------------------------------------------
// Flash attention fp32, 128x128 tiles, 256 threads, 8x8 per-thread scores.
// Online softmax; P staged transposed in smem for the PV product.
// ---------------------------------------------------------------------------
#define QT 128
#define KT 128
#define PADQ 132
#define PADV 68

__global__ __launch_bounds__(256) void attn_kernel(
    const int* __restrict__ mask,
    const float* __restrict__ Q, const float* __restrict__ K,
    const float* __restrict__ V, float* __restrict__ O)
{
    extern __shared__ float smf[];
    float* QsT = smf;                      // [64][132]  QsT[k][r]
    float* KsT = QsT + 64 * PADQ;          // [64][132]  KsT[k][c]
    float* Vs  = KsT + 64 * PADQ;          // [128][68]  Vs[kv][d]
    float* PsT = Vs + 128 * PADV;          // [128][132] PsT[kv][r]

    const int qt = blockIdx.x;
    const int h  = blockIdx.y;
    const int b  = blockIdx.z;
    const int tid = threadIdx.x;
    const int tr = tid >> 4;
    const int tc = tid & 15;

    const int r0 = tr * 4, r1 = 64 + tr * 4;
    const int c0 = tc * 4, c1 = 64 + tc * 4;

    const size_t bh = (size_t)b * Hq + h;
    const float* Qb = Q + (bh * Sq + (size_t)qt * QT) * DKq;
    const float* Kb = K + bh * Sq * DKq;
    const float* Vb = V + bh * Sq * DKq;

    // Load Q tile transposed: QsT[k][r]
    {
        const float4* Qb4 = (const float4*)Qb;
        for (int i = tid; i < QT * 16; i += 256) {
            int r = i >> 4;
            int k4 = (i & 15) << 2;
            float4 t = Qb4[i];
            QsT[(k4 + 0) * PADQ + r] = t.x;
            QsT[(k4 + 1) * PADQ + r] = t.y;
            QsT[(k4 + 2) * PADQ + r] = t.z;
            QsT[(k4 + 3) * PADQ + r] = t.w;
        }
    }

    float o[8][4];
#pragma unroll
    for (int i = 0; i < 8; i++)
#pragma unroll
        for (int j = 0; j < 4; j++) o[i][j] = 0.f;
    float mrow[8], lrow[8];
#pragma unroll
    for (int i = 0; i < 8; i++) { mrow[i] = -1e30f; lrow[i] = 0.f; }

    const int qbase = qt * QT;

    for (int kt = 0; kt < Sq / KT; kt++) {
        __syncthreads();   // prior PV done before overwriting K/V/P
        {
            const float4* Kt4 = (const float4*)(Kb + (size_t)kt * KT * DKq);
            const float4* Vt4 = (const float4*)(Vb + (size_t)kt * KT * DKq);
            for (int i = tid; i < KT * 16; i += 256) {
                int c = i >> 4;
                int k4 = (i & 15) << 2;
                float4 t = Kt4[i];
                KsT[(k4 + 0) * PADQ + c] = t.x;
                KsT[(k4 + 1) * PADQ + c] = t.y;
                KsT[(k4 + 2) * PADQ + c] = t.z;
                KsT[(k4 + 3) * PADQ + c] = t.w;
            }
            for (int i = tid; i < KT * 16; i += 256) {
                int kv = i >> 4;
                int d4 = (i & 15) << 2;
                *(float4*)&Vs[kv * PADV + d4] = Vt4[i];
            }
        }
        __syncthreads();

        // ---- QK^T: s[8][8]
        float s[8][8];
#pragma unroll
        for (int i = 0; i < 8; i++)
#pragma unroll
            for (int j = 0; j < 8; j++) s[i][j] = 0.f;

#pragma unroll 4
        for (int k = 0; k < 64; k++) {
            float4 qa = *(const float4*)&QsT[k * PADQ + r0];
            float4 qb = *(const float4*)&QsT[k * PADQ + r1];
            float4 ka = *(const float4*)&KsT[k * PADQ + c0];
            float4 kb = *(const float4*)&KsT[k * PADQ + c1];
            float qv[8] = {qa.x, qa.y, qa.z, qa.w, qb.x, qb.y, qb.z, qb.w};
            float kv[8] = {ka.x, ka.y, ka.z, ka.w, kb.x, kb.y, kb.z, kb.w};
#pragma unroll
            for (int i = 0; i < 8; i++)
#pragma unroll
                for (int j = 0; j < 8; j++) s[i][j] += qv[i] * kv[j];
        }

        // ---- mask + scale
#pragma unroll
        for (int i = 0; i < 8; i++) {
            int row = qbase + ((i < 4) ? (r0 + i) : (r1 + i - 4));
            const int* mrp = mask + ((size_t)b * Sq + row) * Sq + kt * KT;
            int4 ma = *(const int4*)&mrp[c0];
            int4 mb = *(const int4*)&mrp[c1];
            s[i][0] = ma.x ? s[i][0] * 0.125f : -1e9f;
            s[i][1] = ma.y ? s[i][1] * 0.125f : -1e9f;
            s[i][2] = ma.z ? s[i][2] * 0.125f : -1e9f;
            s[i][3] = ma.w ? s[i][3] * 0.125f : -1e9f;
            s[i][4] = mb.x ? s[i][4] * 0.125f : -1e9f;
            s[i][5] = mb.y ? s[i][5] * 0.125f : -1e9f;
            s[i][6] = mb.z ? s[i][6] * 0.125f : -1e9f;
            s[i][7] = mb.w ? s[i][7] * 0.125f : -1e9f;
        }

        // ---- online softmax per row
#pragma unroll
        for (int i = 0; i < 8; i++) {
            float mx = s[i][0];
#pragma unroll
            for (int j = 1; j < 8; j++) mx = fmaxf(mx, s[i][j]);
            mx = fmaxf(mx, __shfl_xor_sync(0xffffffffu, mx, 1));
            mx = fmaxf(mx, __shfl_xor_sync(0xffffffffu, mx, 2));
            mx = fmaxf(mx, __shfl_xor_sync(0xffffffffu, mx, 4));
            mx = fmaxf(mx, __shfl_xor_sync(0xffffffffu, mx, 8));
            float mnew = fmaxf(mrow[i], mx);
            float alpha = __expf(mrow[i] - mnew);
            mrow[i] = mnew;
            float sum = 0.f;
#pragma unroll
            for (int j = 0; j < 8; j++) {
                s[i][j] = __expf(s[i][j] - mnew);
                sum += s[i][j];
            }
            sum += __shfl_xor_sync(0xffffffffu, sum, 1);
            sum += __shfl_xor_sync(0xffffffffu, sum, 2);
            sum += __shfl_xor_sync(0xffffffffu, sum, 4);
            sum += __shfl_xor_sync(0xffffffffu, sum, 8);
            lrow[i] = lrow[i] * alpha + sum;
#pragma unroll
            for (int j = 0; j < 4; j++) o[i][j] *= alpha;
        }

        // ---- stage P transposed: PsT[col][row]
#pragma unroll
        for (int j = 0; j < 8; j++) {
            int col = (j < 4) ? (c0 + j) : (c1 + j - 4);
            *(float4*)&PsT[col * PADQ + r0] =
                make_float4(s[0][j], s[1][j], s[2][j], s[3][j]);
            *(float4*)&PsT[col * PADQ + r1] =
                make_float4(s[4][j], s[5][j], s[6][j], s[7][j]);
        }
        __syncthreads();

        // ---- PV: o[i][jd] += P[row_i][kv] * V[kv][tc*4+jd]
#pragma unroll 4
        for (int kv = 0; kv < 128; kv++) {
            float4 pa = *(const float4*)&PsT[kv * PADQ + r0];
            float4 pb = *(const float4*)&PsT[kv * PADQ + r1];
            float4 vv = *(const float4*)&Vs[kv * PADV + c0];
            float pv[8] = {pa.x, pa.y, pa.z, pa.w, pb.x, pb.y, pb.z, pb.w};
#pragma unroll
            for (int i = 0; i < 8; i++) {
                o[i][0] += pv[i] * vv.x;
                o[i][1] += pv[i] * vv.y;
                o[i][2] += pv[i] * vv.z;
                o[i][3] += pv[i] * vv.w;
            }
        }
    }

    // ---- epilogue
#pragma unroll
    for (int i = 0; i < 8; i++) {
        int row = qbase + ((i < 4) ? (r0 + i) : (r1 + i - 4));
        float inv = 1.0f / lrow[i];
        float4 v = make_float4(o[i][0] * inv, o[i][1] * inv,
                               o[i][2] * inv, o[i][3] * inv);
        *(float4*)&O[((size_t)b * Sq + row) * Dq + h * DKq + c0] = v;
    }
}

// ---------------------------------------------------------------------------
extern "C" void kernel_launch(void* const* d_in, const int* in_sizes, int n_in,
                              void* d_out, int out_size)
{
    const float* x    = (const float*)d_in[0];
    const int*   mask = (const int*)  d_in[1];
    const float* Wqp  = (const float*)d_in[2];
    const float* bqp  = (const float*)d_in[3];
    const float* Wkp  = (const float*)d_in[4];
    const float* bkp  = (const float*)d_in[5];
    const float* Wvp  = (const float*)d_in[6];
    const float* bvp  = (const float*)d_in[7];
    const float* Wop  = (const float*)d_in[8];
    const float* bop  = (const float*)d_in[9];
    float* out = (float*)d_out;

    float *qp, *kp, *vp, *op;
    cudaGetSymbolAddress((void**)&qp, g_q);
    cudaGetSymbolAddress((void**)&kp, g_k);
    cudaGetSymbolAddress((void**)&vp, g_v);
    cudaGetSymbolAddress((void**)&op, g_o);

    dim3 gg(768 / 128, Mrows / 128);   // (6, 64)

    gemm_bias_kernel<<<gg, 256>>>(x, Wqp, bqp, qp, 1);
    gemm_bias_kernel<<<gg, 256>>>(x, Wkp, bkp, kp, 1);
    gemm_bias_kernel<<<gg, 256>>>(x, Wvp, bvp, vp, 1);

    const int smem_bytes = (2 * 64 * PADQ + 128 * PADV + 128 * PADQ) * 4; // 169984
    cudaFuncSetAttribute(attn_kernel,
                         cudaFuncAttributeMaxDynamicSharedMemorySize, smem_bytes);
    attn_kernel<<<dim3(Sq / QT, Hq, Bq), 256, smem_bytes>>>(mask, qp, kp, vp, op);

    gemm_bias_kernel<<<gg, 256>>>(op, Wop, bop, out, 0);
}

// round 3
// speedup vs baseline: 6.3922x; 2.0491x over previous
#include <cuda_runtime.h>
#include <cuda_bf16.h>
#include <cstdint>

// Problem constants
#define Bq   2
#define Sq   4096
#define Dq   768
#define Hq   12
#define DKq  64
#define Mrows (Bq*Sq)        // 8192
#define NEGV -1e9f

// Scratch (device globals: allocation-free rule)
__device__ float g_q[(size_t)Bq*Hq*Sq*DKq];   // [B,H,S,DK]
__device__ float g_k[(size_t)Bq*Hq*Sq*DKq];
__device__ float g_v[(size_t)Bq*Hq*Sq*DKq];
__device__ float g_o[(size_t)Bq*Sq*Dq];       // [B,S,D]

// ---------------------------------------------------------------------------
// GEMM: C = A @ W^T + bias (fp32, unchanged from round 2 — known good)
// ---------------------------------------------------------------------------
__global__ __launch_bounds__(256) void gemm_bias_kernel(
    const float* __restrict__ A, const float* __restrict__ W,
    const float* __restrict__ bias, float* __restrict__ C, int split)
{
    __shared__ float AsT[16][132];
    __shared__ float WsT[16][132];

    const int tid = threadIdx.x;
    const int tr = tid >> 4;
    const int tc = tid & 15;
    const int m0 = blockIdx.y * 128;
    const int n0 = blockIdx.x * 128;

    const int r0 = tr * 4, r1 = 64 + tr * 4;
    const int c0 = tc * 4, c1 = 64 + tc * 4;

    float acc[8][8];
#pragma unroll
    for (int i = 0; i < 8; i++)
#pragma unroll
        for (int j = 0; j < 8; j++) acc[i][j] = 0.f;

    for (int k0 = 0; k0 < 768; k0 += 16) {
        const float4* A4 = (const float4*)(A + (size_t)m0 * 768 + k0);
        const float4* W4 = (const float4*)(W + (size_t)n0 * 768 + k0);
#pragma unroll
        for (int i = tid; i < 512; i += 256) {
            int mm = i >> 2;
            int kq = (i & 3) << 2;
            float4 t = A4[(size_t)mm * 192 + (i & 3)];
            AsT[kq + 0][mm] = t.x;
            AsT[kq + 1][mm] = t.y;
            AsT[kq + 2][mm] = t.z;
            AsT[kq + 3][mm] = t.w;
        }
#pragma unroll
        for (int i = tid; i < 512; i += 256) {
            int nn = i >> 2;
            int kq = (i & 3) << 2;
            float4 t = W4[(size_t)nn * 192 + (i & 3)];
            WsT[kq + 0][nn] = t.x;
            WsT[kq + 1][nn] = t.y;
            WsT[kq + 2][nn] = t.z;
            WsT[kq + 3][nn] = t.w;
        }
        __syncthreads();

#pragma unroll
        for (int kk = 0; kk < 16; kk++) {
            float4 a0 = *(const float4*)&AsT[kk][r0];
            float4 a1 = *(const float4*)&AsT[kk][r1];
            float4 w0 = *(const float4*)&WsT[kk][c0];
            float4 w1 = *(const float4*)&WsT[kk][c1];
            float a[8] = {a0.x, a0.y, a0.z, a0.w, a1.x, a1.y, a1.z, a1.w};
            float w[8] = {w0.x, w0.y, w0.z, w0.w, w1.x, w1.y, w1.z, w1.w};
#pragma unroll
            for (int i = 0; i < 8; i++)
#pragma unroll
                for (int j = 0; j < 8; j++) acc[i][j] += a[i] * w[j];
        }
        __syncthreads();
    }

    float4 b0 = *(const float4*)&bias[n0 + c0];
    float4 b1 = *(const float4*)&bias[n0 + c1];

    const int h0 = (n0 + c0) >> 6, dk0 = (n0 + c0) & 63;
    const int h1 = (n0 + c1) >> 6, dk1 = (n0 + c1) & 63;

#pragma unroll
    for (int i = 0; i < 8; i++) {
        int m = m0 + ((i < 4) ? (r0 + i) : (r1 + i - 4));
        float4 v0 = make_float4(acc[i][0] + b0.x, acc[i][1] + b0.y,
                                acc[i][2] + b0.z, acc[i][3] + b0.w);
        float4 v1 = make_float4(acc[i][4] + b1.x, acc[i][5] + b1.y,
                                acc[i][6] + b1.z, acc[i][7] + b1.w);
        if (split) {
            int bb = m >> 12;
            int ss = m & 4095;
            *(float4*)&C[(((size_t)bb * Hq + h0) * Sq + ss) * DKq + dk0] = v0;
            *(float4*)&C[(((size_t)bb * Hq + h1) * Sq + ss) * DKq + dk1] = v1;
        } else {
            *(float4*)&C[(size_t)m * 768 + n0 + c0] = v0;
            *(float4*)&C[(size_t)m * 768 + n0 + c1] = v1;
        }
    }
}

// ---------------------------------------------------------------------------
// tf32 tensor-core helpers
// ---------------------------------------------------------------------------
__device__ __forceinline__ float tf32rf(float x) {
    uint32_t r;
    asm("cvt.rna.tf32.f32 %0, %1;" : "=r"(r) : "f"(x));
    return __uint_as_float(r);
}

__device__ __forceinline__ void mma_tf32(float c[4],
    uint32_t a0, uint32_t a1, uint32_t a2, uint32_t a3,
    uint32_t b0, uint32_t b1)
{
    asm volatile(
        "mma.sync.aligned.m16n8k8.row.col.f32.tf32.tf32.f32 "
        "{%0,%1,%2,%3},{%4,%5,%6,%7},{%8,%9},{%0,%1,%2,%3};"
        : "+f"(c[0]), "+f"(c[1]), "+f"(c[2]), "+f"(c[3])
        : "r"(a0), "r"(a1), "r"(a2), "r"(a3), "r"(b0), "r"(b1));
}

// ---------------------------------------------------------------------------
// Flash attention with tf32 mma. CTA = 128 q-rows; per iter 64 kv.
// 8 warps, warp w owns q-rows [w*16, w*16+16). Online softmax in frags.
// smem: Qs[128][68] Ks[64][68] Vs[64][72] Ps[8][16][68] = 105472 B -> 2 CTA/SM
// ---------------------------------------------------------------------------
__global__ __launch_bounds__(256, 2) void attn_tc_kernel(
    const int* __restrict__ mask,
    const float* __restrict__ Q, const float* __restrict__ K,
    const float* __restrict__ V, float* __restrict__ O)
{
    extern __shared__ float sm[];
    float* Qs = sm;                     // [128][68]
    float* Ks = sm + 128 * 68;          // [64][68]
    float* Vs = Ks + 64 * 68;           // [64][72]
    float* Psb = Vs + 64 * 72;          // [8][16][68]

    const int tid  = threadIdx.x;
    const int w    = tid >> 5;
    const int lane = tid & 31;
    const int g    = lane >> 2;
    const int tig  = lane & 3;
    float* Psw = Psb + w * (16 * 68);

    const int qt = blockIdx.x;
    const int h  = blockIdx.y;
    const int b  = blockIdx.z;
    const size_t bh = (size_t)b * Hq + h;
    const float* Qb = Q + (bh * Sq + (size_t)qt * 128) * DKq;
    const float* Kb = K + bh * Sq * DKq;
    const float* Vb = V + bh * Sq * DKq;

    // Q tile: pre-scale by 1/sqrt(dk) and round to tf32
    {
        const float4* Q4 = (const float4*)Qb;
#pragma unroll
        for (int it = 0; it < 8; it++) {
            int i = tid + it * 256;
            int r = i >> 4, k4 = (i & 15) << 2;
            float4 t = Q4[i];
            float* dst = &Qs[r * 68 + k4];
            dst[0] = tf32rf(t.x * 0.125f);
            dst[1] = tf32rf(t.y * 0.125f);
            dst[2] = tf32rf(t.z * 0.125f);
            dst[3] = tf32rf(t.w * 0.125f);
        }
    }

    float o[8][4];
#pragma unroll
    for (int nt = 0; nt < 8; nt++)
#pragma unroll
        for (int j = 0; j < 4; j++) o[nt][j] = 0.f;
    float m0 = -1e30f, m1 = -1e30f, l0 = 0.f, l1 = 0.f;

    const int row0 = qt * 128 + w * 16 + g;       // this thread's row pair
    const int2* mrow0 = (const int2*)(mask + ((size_t)b * Sq + row0) * Sq);
    const int2* mrow1 = (const int2*)(mask + ((size_t)b * Sq + row0 + 8) * Sq);

    for (int kt = 0; kt < Sq / 64; kt++) {
        __syncthreads();   // prior PV reads of Vs complete
        {
            const float4* K4 = (const float4*)(Kb + (size_t)kt * 64 * DKq);
            const float4* V4 = (const float4*)(Vb + (size_t)kt * 64 * DKq);
#pragma unroll
            for (int it = 0; it < 4; it++) {
                int i = tid + it * 256;
                int r = i >> 4, k4 = (i & 15) << 2;
                float4 tk = K4[i];
                float4 tv = V4[i];
                float* dk = &Ks[r * 68 + k4];
                dk[0] = tf32rf(tk.x); dk[1] = tf32rf(tk.y);
                dk[2] = tf32rf(tk.z); dk[3] = tf32rf(tk.w);
                float* dv = &Vs[r * 72 + k4];
                dv[0] = tf32rf(tv.x); dv[1] = tf32rf(tv.y);
                dv[2] = tf32rf(tv.z); dv[3] = tf32rf(tv.w);
            }
        }
        __syncthreads();

        // ---- S = Q K^T  (per warp: 16 x 64)
        float cs[8][4];
#pragma unroll
        for (int nt = 0; nt < 8; nt++)
#pragma unroll
            for (int j = 0; j < 4; j++) cs[nt][j] = 0.f;

#pragma unroll
        for (int ks = 0; ks < 8; ks++) {
            const float* qp = &Qs[(w * 16 + g) * 68 + ks * 8 + tig];
            uint32_t a0 = __float_as_uint(qp[0]);
            uint32_t a2 = __float_as_uint(qp[4]);
            uint32_t a1 = __float_as_uint(qp[8 * 68]);
            uint32_t a3 = __float_as_uint(qp[8 * 68 + 4]);
#pragma unroll
            for (int nt = 0; nt < 8; nt++) {
                const float* kp = &Ks[(nt * 8 + g) * 68 + ks * 8 + tig];
                uint32_t b0 = __float_as_uint(kp[0]);
                uint32_t b1 = __float_as_uint(kp[4]);
                mma_tf32(cs[nt], a0, a1, a2, a3, b0, b1);
            }
        }

        // ---- mask (Q pre-scaled, so masked lanes -> NEG)
        const int mbase = kt * 32;   // int2 index base (64 ints)
#pragma unroll
        for (int nt = 0; nt < 8; nt++) {
            int2 u0 = mrow0[mbase + nt * 4 + tig];
            int2 u1 = mrow1[mbase + nt * 4 + tig];
            cs[nt][0] = u0.x ? cs[nt][0] : NEGV;
            cs[nt][1] = u0.y ? cs[nt][1] : NEGV;
            cs[nt][2] = u1.x ? cs[nt][2] : NEGV;
            cs[nt][3] = u1.y ? cs[nt][3] : NEGV;
        }

        // ---- online softmax (rows g and g+8 of this warp's slab)
        float mx0 = NEGV, mx1 = NEGV;
#pragma unroll
        for (int nt = 0; nt < 8; nt++) {
            mx0 = fmaxf(mx0, fmaxf(cs[nt][0], cs[nt][1]));
            mx1 = fmaxf(mx1, fmaxf(cs[nt][2], cs[nt][3]));
        }
        mx0 = fmaxf(mx0, __shfl_xor_sync(0xffffffffu, mx0, 1));
        mx0 = fmaxf(mx0, __shfl_xor_sync(0xffffffffu, mx0, 2));
        mx1 = fmaxf(mx1, __shfl_xor_sync(0xffffffffu, mx1, 1));
        mx1 = fmaxf(mx1, __shfl_xor_sync(0xffffffffu, mx1, 2));
        float mn0 = fmaxf(m0, mx0), mn1 = fmaxf(m1, mx1);
        float al0 = __expf(m0 - mn0), al1 = __expf(m1 - mn1);
        m0 = mn0; m1 = mn1;

        float s0 = 0.f, s1 = 0.f;
#pragma unroll
        for (int nt = 0; nt < 8; nt++) {
            float p00 = __expf(cs[nt][0] - mn0);
            float p01 = __expf(cs[nt][1] - mn0);
            float p10 = __expf(cs[nt][2] - mn1);
            float p11 = __expf(cs[nt][3] - mn1);
            s0 += p00 + p01;
            s1 += p10 + p11;
            *(float2*)&Psw[g * 68 + nt * 8 + 2 * tig] =
                make_float2(tf32rf(p00), tf32rf(p01));
            *(float2*)&Psw[(g + 8) * 68 + nt * 8 + 2 * tig] =
                make_float2(tf32rf(p10), tf32rf(p11));
        }
        s0 += __shfl_xor_sync(0xffffffffu, s0, 1);
        s0 += __shfl_xor_sync(0xffffffffu, s0, 2);
        s1 += __shfl_xor_sync(0xffffffffu, s1, 1);
        s1 += __shfl_xor_sync(0xffffffffu, s1, 2);
        l0 = l0 * al0 + s0;
        l1 = l1 * al1 + s1;
#pragma unroll
        for (int nt = 0; nt < 8; nt++) {
            o[nt][0] *= al0; o[nt][1] *= al0;
            o[nt][2] *= al1; o[nt][3] *= al1;
        }
        __syncwarp();   // P staged (warp-private buffer)

        // ---- O += P V  (per warp: 16 x 64, k = 64 kv)
#pragma unroll
        for (int ks = 0; ks < 8; ks++) {
            const float* pp = &Psw[g * 68 + ks * 8 + tig];
            uint32_t a0 = __float_as_uint(pp[0]);
            uint32_t a2 = __float_as_uint(pp[4]);
            uint32_t a1 = __float_as_uint(pp[8 * 68]);
            uint32_t a3 = __float_as_uint(pp[8 * 68 + 4]);
#pragma unroll
            for (int nt = 0; nt < 8; nt++) {
                const float* vp = &Vs[(ks * 8 + tig) * 72 + nt * 8 + g];
                uint32_t b0 = __float_as_uint(vp[0]);
                uint32_t b1 = __float_as_uint(vp[4 * 72]);
                mma_tf32(o[nt], a0, a1, a2, a3, b0, b1);
            }
        }
        __syncwarp();   // PV reads of Psw done before next-iter overwrite
    }

    // ---- epilogue
    const float inv0 = 1.0f / l0, inv1 = 1.0f / l1;
    float* op0 = O + ((size_t)b * Sq + row0) * Dq + h * DKq;
    float* op1 = O + ((size_t)b * Sq + row0 + 8) * Dq + h * DKq;
#pragma unroll
    for (int nt = 0; nt < 8; nt++) {
        *(float2*)&op0[nt * 8 + 2 * tig] =
            make_float2(o[nt][0] * inv0, o[nt][1] * inv0);
        *(float2*)&op1[nt * 8 + 2 * tig] =
            make_float2(o[nt][2] * inv1, o[nt][3] * inv1);
    }
}

// ---------------------------------------------------------------------------
extern "C" void kernel_launch(void* const* d_in, const int* in_sizes, int n_in,
                              void* d_out, int out_size)
{
    const float* x    = (const float*)d_in[0];
    const int*   mask = (const int*)  d_in[1];
    const float* Wqp  = (const float*)d_in[2];
    const float* bqp  = (const float*)d_in[3];
    const float* Wkp  = (const float*)d_in[4];
    const float* bkp  = (const float*)d_in[5];
    const float* Wvp  = (const float*)d_in[6];
    const float* bvp  = (const float*)d_in[7];
    const float* Wop  = (const float*)d_in[8];
    const float* bop  = (const float*)d_in[9];
    float* out = (float*)d_out;

    float *qp, *kp, *vp, *op;
    cudaGetSymbolAddress((void**)&qp, g_q);
    cudaGetSymbolAddress((void**)&kp, g_k);
    cudaGetSymbolAddress((void**)&vp, g_v);
    cudaGetSymbolAddress((void**)&op, g_o);

    dim3 gg(768 / 128, Mrows / 128);   // (6, 64)

    gemm_bias_kernel<<<gg, 256>>>(x, Wqp, bqp, qp, 1);
    gemm_bias_kernel<<<gg, 256>>>(x, Wkp, bkp, kp, 1);
    gemm_bias_kernel<<<gg, 256>>>(x, Wvp, bvp, vp, 1);

    const int smem_bytes = (128 * 68 + 64 * 68 + 64 * 72 + 8 * 16 * 68) * 4; // 105472
    cudaFuncSetAttribute(attn_tc_kernel,
                         cudaFuncAttributeMaxDynamicSharedMemorySize, smem_bytes);
    attn_tc_kernel<<<dim3(Sq / 128, Hq, Bq), 256, smem_bytes>>>(mask, qp, kp, vp, op);

    gemm_bias_kernel<<<gg, 256>>>(op, Wop, bop, out, 0);
}

// round 4
// speedup vs baseline: 6.9290x; 1.0840x over previous
#include <cuda_runtime.h>
#include <cuda_bf16.h>
#include <cstdint>

// Problem constants
#define Bq   2
#define Sq   4096
#define Dq   768
#define Hq   12
#define DKq  64
#define Mrows (Bq*Sq)        // 8192
#define NEGV -1e9f

// Scratch (device globals: allocation-free rule)
__device__ float g_q[(size_t)Bq*Hq*Sq*DKq];   // [B,H,S,DK]
__device__ float g_k[(size_t)Bq*Hq*Sq*DKq];
__device__ float g_v[(size_t)Bq*Hq*Sq*DKq];
__device__ float g_o[(size_t)Bq*Sq*Dq];       // [B,S,D]

// ---------------------------------------------------------------------------
// tf32 helpers
// ---------------------------------------------------------------------------
__device__ __forceinline__ float tf32rf(float x) {
    uint32_t r;
    asm("cvt.rna.tf32.f32 %0, %1;" : "=r"(r) : "f"(x));
    return __uint_as_float(r);
}
__device__ __forceinline__ uint32_t tf32u(float x) {
    uint32_t r;
    asm("cvt.rna.tf32.f32 %0, %1;" : "=r"(r) : "f"(x));
    return r;
}
__device__ __forceinline__ void mma_tf32(float c[4],
    uint32_t a0, uint32_t a1, uint32_t a2, uint32_t a3,
    uint32_t b0, uint32_t b1)
{
    asm volatile(
        "mma.sync.aligned.m16n8k8.row.col.f32.tf32.tf32.f32 "
        "{%0,%1,%2,%3},{%4,%5,%6,%7},{%8,%9},{%0,%1,%2,%3};"
        : "+f"(c[0]), "+f"(c[1]), "+f"(c[2]), "+f"(c[3])
        : "r"(a0), "r"(a1), "r"(a2), "r"(a3), "r"(b0), "r"(b1));
}

// ---------------------------------------------------------------------------
// tf32 GEMM: C = A @ W^T + bias.  A:[M,768], W:[N,768].
// CTA tile 128x128, k-chunk 32, 8 warps; warp w -> rows [16w,16w+16), all n.
// smem swizzled: off(r,k) = r*32 + (k ^ ((r&3)<<3))
// ---------------------------------------------------------------------------
__device__ __forceinline__ int gsw(int r, int k) {
    return r * 32 + (k ^ ((r & 3) << 3));
}

__global__ __launch_bounds__(256) void gemm_tc_kernel(
    const float* __restrict__ A, const float* __restrict__ W,
    const float* __restrict__ bias, float* __restrict__ C, int split)
{
    __shared__ float As[128 * 32];
    __shared__ float Ws[128 * 32];

    const int tid  = threadIdx.x;
    const int w    = tid >> 5;
    const int lane = tid & 31;
    const int g    = lane >> 2;
    const int t    = lane & 3;
    const int m0 = blockIdx.y * 128;
    const int n0 = blockIdx.x * 128;

    float acc[16][4];
#pragma unroll
    for (int nt = 0; nt < 16; nt++)
#pragma unroll
        for (int j = 0; j < 4; j++) acc[nt][j] = 0.f;

    const int ra = w * 16 + g;          // A-frag row (and +8)
    const int swa = (g & 3) << 3;

    for (int k0 = 0; k0 < 768; k0 += 32) {
        __syncthreads();
        const float4* A4 = (const float4*)(A + (size_t)m0 * 768 + k0);
        const float4* W4 = (const float4*)(W + (size_t)n0 * 768 + k0);
#pragma unroll
        for (int it = 0; it < 4; it++) {
            int i = tid + it * 256;
            int m = i >> 3, k4 = (i & 7) << 2;
            float4 v = A4[(size_t)m * 192 + (i & 7)];
            *(float4*)&As[gsw(m, k4)] =
                make_float4(tf32rf(v.x), tf32rf(v.y), tf32rf(v.z), tf32rf(v.w));
            float4 u = W4[(size_t)m * 192 + (i & 7)];
            *(float4*)&Ws[gsw(m, k4)] =
                make_float4(tf32rf(u.x), tf32rf(u.y), tf32rf(u.z), tf32rf(u.w));
        }
        __syncthreads();

#pragma unroll
        for (int ks = 0; ks < 4; ks++) {
            int kk = ks * 8 + 2 * t;
            float2 fa0 = *(const float2*)&As[ra * 32 + (kk ^ swa)];
            float2 fa1 = *(const float2*)&As[(ra + 8) * 32 + (kk ^ swa)];
            uint32_t a0 = __float_as_uint(fa0.x);
            uint32_t a2 = __float_as_uint(fa0.y);
            uint32_t a1 = __float_as_uint(fa1.x);
            uint32_t a3 = __float_as_uint(fa1.y);
#pragma unroll
            for (int nt = 0; nt < 16; nt++) {
                int rn = nt * 8 + g;
                float2 fb = *(const float2*)&Ws[rn * 32 + (kk ^ ((g & 3) << 3))];
                mma_tf32(acc[nt], a0, a1, a2, a3,
                         __float_as_uint(fb.x), __float_as_uint(fb.y));
            }
        }
    }

    // epilogue
#pragma unroll
    for (int nt = 0; nt < 16; nt++) {
        int n = n0 + nt * 8 + 2 * t;
        float2 bv = *(const float2*)&bias[n];
        int ma = m0 + w * 16 + g;
        int mb = ma + 8;
        float2 v0 = make_float2(acc[nt][0] + bv.x, acc[nt][1] + bv.y);
        float2 v1 = make_float2(acc[nt][2] + bv.x, acc[nt][3] + bv.y);
        if (split) {
            int hh = n >> 6, dk = n & 63;
            int ba = ma >> 12, sa = ma & 4095;
            int bb = mb >> 12, sb = mb & 4095;
            *(float2*)&C[(((size_t)ba * Hq + hh) * Sq + sa) * DKq + dk] = v0;
            *(float2*)&C[(((size_t)bb * Hq + hh) * Sq + sb) * DKq + dk] = v1;
        } else {
            *(float2*)&C[(size_t)ma * 768 + n] = v0;
            *(float2*)&C[(size_t)mb * 768 + n] = v1;
        }
    }
}

// ---------------------------------------------------------------------------
// Flash attention tf32, register-passed P (QK C-frag == PV A-frag via k
// relabel t<->2t, t+4<->2t+1). Q A-frags in registers. K swizzled in smem,
// V transposed in smem (VsT[d][kv], stride 68).
// CTA: 128 q-rows, 8 warps x 16 rows; KV tile 64.
// ---------------------------------------------------------------------------
#define VSTR 68
__device__ __forceinline__ int ksw(int r, int k) {
    return r * 64 + (k ^ ((r & 7) << 3));
}

__global__ __launch_bounds__(256, 2) void attn_tc_kernel(
    const int* __restrict__ mask,
    const float* __restrict__ Q, const float* __restrict__ K,
    const float* __restrict__ V, float* __restrict__ O)
{
    __shared__ float Ks[64 * 64];
    __shared__ float VsT[64 * VSTR];

    const int tid  = threadIdx.x;
    const int w    = tid >> 5;
    const int lane = tid & 31;
    const int g    = lane >> 2;
    const int t    = lane & 3;

    const int qt = blockIdx.x;
    const int h  = blockIdx.y;
    const int b  = blockIdx.z;
    const size_t bh = (size_t)b * Hq + h;
    const float* Qb = Q + (bh * Sq + (size_t)qt * 128) * DKq;
    const float* Kb = K + bh * Sq * DKq;
    const float* Vb = V + bh * Sq * DKq;

    // Q A-frags in registers (pre-scaled, tf32)
    uint32_t qa[8][4];
    {
        const float* Qr0 = Qb + (size_t)(w * 16 + g) * DKq;
#pragma unroll
        for (int ks = 0; ks < 8; ks++) {
            float2 t0 = *(const float2*)&Qr0[ks * 8 + 2 * t];
            float2 t1 = *(const float2*)&Qr0[8 * DKq + ks * 8 + 2 * t];
            qa[ks][0] = tf32u(t0.x * 0.125f);
            qa[ks][2] = tf32u(t0.y * 0.125f);
            qa[ks][1] = tf32u(t1.x * 0.125f);
            qa[ks][3] = tf32u(t1.y * 0.125f);
        }
    }

    float o[8][4];
#pragma unroll
    for (int nt = 0; nt < 8; nt++)
#pragma unroll
        for (int j = 0; j < 4; j++) o[nt][j] = 0.f;
    float m0 = -1e30f, m1 = -1e30f, l0 = 0.f, l1 = 0.f;

    const int row0 = qt * 128 + w * 16 + g;
    const int2* mrow0 = (const int2*)(mask + ((size_t)b * Sq + row0) * Sq);
    const int2* mrow1 = (const int2*)(mask + ((size_t)b * Sq + row0 + 8) * Sq);

    for (int kt = 0; kt < Sq / 64; kt++) {
        __syncthreads();
        {
            const float4* K4 = (const float4*)(Kb + (size_t)kt * 64 * DKq);
            const float4* V4 = (const float4*)(Vb + (size_t)kt * 64 * DKq);
#pragma unroll
            for (int it = 0; it < 4; it++) {
                int i = tid + it * 256;
                int r = i >> 4, k4 = (i & 15) << 2;
                float4 kk = K4[i];
                *(float4*)&Ks[ksw(r, k4)] =
                    make_float4(tf32rf(kk.x), tf32rf(kk.y),
                                tf32rf(kk.z), tf32rf(kk.w));
                float4 vv = V4[i];
                VsT[(k4 + 0) * VSTR + r] = tf32rf(vv.x);
                VsT[(k4 + 1) * VSTR + r] = tf32rf(vv.y);
                VsT[(k4 + 2) * VSTR + r] = tf32rf(vv.z);
                VsT[(k4 + 3) * VSTR + r] = tf32rf(vv.w);
            }
        }
        __syncthreads();

        // ---- S = Q K^T (warp: 16 x 64)
        float cs[8][4];
#pragma unroll
        for (int nt = 0; nt < 8; nt++)
#pragma unroll
            for (int j = 0; j < 4; j++) cs[nt][j] = 0.f;

#pragma unroll
        for (int ks = 0; ks < 8; ks++) {
            int kk = ks * 8 + 2 * t;
#pragma unroll
            for (int nt = 0; nt < 8; nt++) {
                int rn = nt * 8 + g;
                float2 fb = *(const float2*)&Ks[rn * 64 + (kk ^ (g << 3))];
                mma_tf32(cs[nt], qa[ks][0], qa[ks][1], qa[ks][2], qa[ks][3],
                         __float_as_uint(fb.x), __float_as_uint(fb.y));
            }
        }

        // ---- mask
        const int mbase = kt * 32;
#pragma unroll
        for (int nt = 0; nt < 8; nt++) {
            int2 u0 = mrow0[mbase + nt * 4 + t];
            int2 u1 = mrow1[mbase + nt * 4 + t];
            cs[nt][0] = u0.x ? cs[nt][0] : NEGV;
            cs[nt][1] = u0.y ? cs[nt][1] : NEGV;
            cs[nt][2] = u1.x ? cs[nt][2] : NEGV;
            cs[nt][3] = u1.y ? cs[nt][3] : NEGV;
        }

        // ---- online softmax (rows g and g+8)
        float mx0 = NEGV, mx1 = NEGV;
#pragma unroll
        for (int nt = 0; nt < 8; nt++) {
            mx0 = fmaxf(mx0, fmaxf(cs[nt][0], cs[nt][1]));
            mx1 = fmaxf(mx1, fmaxf(cs[nt][2], cs[nt][3]));
        }
        mx0 = fmaxf(mx0, __shfl_xor_sync(0xffffffffu, mx0, 1));
        mx0 = fmaxf(mx0, __shfl_xor_sync(0xffffffffu, mx0, 2));
        mx1 = fmaxf(mx1, __shfl_xor_sync(0xffffffffu, mx1, 1));
        mx1 = fmaxf(mx1, __shfl_xor_sync(0xffffffffu, mx1, 2));
        float mn0 = fmaxf(m0, mx0), mn1 = fmaxf(m1, mx1);
        float al0 = __expf(m0 - mn0), al1 = __expf(m1 - mn1);
        m0 = mn0; m1 = mn1;

        float s0 = 0.f, s1 = 0.f;
#pragma unroll
        for (int nt = 0; nt < 8; nt++) {
            float p00 = __expf(cs[nt][0] - mn0);
            float p01 = __expf(cs[nt][1] - mn0);
            float p10 = __expf(cs[nt][2] - mn1);
            float p11 = __expf(cs[nt][3] - mn1);
            s0 += p00 + p01;
            s1 += p10 + p11;
            // store tf32-converted P bits in place (A-frag for PV)
            cs[nt][0] = __uint_as_float(tf32u(p00));
            cs[nt][1] = __uint_as_float(tf32u(p01));
            cs[nt][2] = __uint_as_float(tf32u(p10));
            cs[nt][3] = __uint_as_float(tf32u(p11));
        }
        s0 += __shfl_xor_sync(0xffffffffu, s0, 1);
        s0 += __shfl_xor_sync(0xffffffffu, s0, 2);
        s1 += __shfl_xor_sync(0xffffffffu, s1, 1);
        s1 += __shfl_xor_sync(0xffffffffu, s1, 2);
        l0 = l0 * al0 + s0;
        l1 = l1 * al1 + s1;
#pragma unroll
        for (int nt = 0; nt < 8; nt++) {
            o[nt][0] *= al0; o[nt][1] *= al0;
            o[nt][2] *= al1; o[nt][3] *= al1;
        }

        // ---- O += P V  (A-frag = register-passed P; B from VsT)
#pragma unroll
        for (int s = 0; s < 8; s++) {
            uint32_t a0 = __float_as_uint(cs[s][0]);
            uint32_t a2 = __float_as_uint(cs[s][1]);
            uint32_t a1 = __float_as_uint(cs[s][2]);
            uint32_t a3 = __float_as_uint(cs[s][3]);
            int kk = s * 8 + 2 * t;
#pragma unroll
            for (int nt = 0; nt < 8; nt++) {
                float2 fb = *(const float2*)&VsT[(nt * 8 + g) * VSTR + kk];
                mma_tf32(o[nt], a0, a1, a2, a3,
                         __float_as_uint(fb.x), __float_as_uint(fb.y));
            }
        }
    }

    // ---- epilogue
    const float inv0 = 1.0f / l0, inv1 = 1.0f / l1;
    float* op0 = O + ((size_t)b * Sq + row0) * Dq + h * DKq;
    float* op1 = O + ((size_t)b * Sq + row0 + 8) * Dq + h * DKq;
#pragma unroll
    for (int nt = 0; nt < 8; nt++) {
        *(float2*)&op0[nt * 8 + 2 * t] =
            make_float2(o[nt][0] * inv0, o[nt][1] * inv0);
        *(float2*)&op1[nt * 8 + 2 * t] =
            make_float2(o[nt][2] * inv1, o[nt][3] * inv1);
    }
}

// ---------------------------------------------------------------------------
extern "C" void kernel_launch(void* const* d_in, const int* in_sizes, int n_in,
                              void* d_out, int out_size)
{
    const float* x    = (const float*)d_in[0];
    const int*   mask = (const int*)  d_in[1];
    const float* Wqp  = (const float*)d_in[2];
    const float* bqp  = (const float*)d_in[3];
    const float* Wkp  = (const float*)d_in[4];
    const float* bkp  = (const float*)d_in[5];
    const float* Wvp  = (const float*)d_in[6];
    const float* bvp  = (const float*)d_in[7];
    const float* Wop  = (const float*)d_in[8];
    const float* bop  = (const float*)d_in[9];
    float* out = (float*)d_out;

    float *qp, *kp, *vp, *op;
    cudaGetSymbolAddress((void**)&qp, g_q);
    cudaGetSymbolAddress((void**)&kp, g_k);
    cudaGetSymbolAddress((void**)&vp, g_v);
    cudaGetSymbolAddress((void**)&op, g_o);

    dim3 gg(768 / 128, Mrows / 128);   // (6, 64)

    gemm_tc_kernel<<<gg, 256>>>(x, Wqp, bqp, qp, 1);
    gemm_tc_kernel<<<gg, 256>>>(x, Wkp, bkp, kp, 1);
    gemm_tc_kernel<<<gg, 256>>>(x, Wvp, bvp, vp, 1);

    attn_tc_kernel<<<dim3(Sq / 128, Hq, Bq), 256>>>(mask, qp, kp, vp, op);

    gemm_tc_kernel<<<gg, 256>>>(op, Wop, bop, out, 0);
}

// round 5
// speedup vs baseline: 8.2677x; 1.1932x over previous
#include <cuda_runtime.h>
#include <cuda_bf16.h>
#include <cstdint>

// Problem constants
#define Bq   2
#define Sq   4096
#define Dq   768
#define Hq   12
#define DKq  64
#define Mrows (Bq*Sq)        // 8192
#define NEGV -1e9f

// Scratch (device globals: allocation-free rule)
__device__ float g_q[(size_t)Bq*Hq*Sq*DKq];   // [B,H,S,DK]
__device__ float g_k[(size_t)Bq*Hq*Sq*DKq];
__device__ float g_v[(size_t)Bq*Hq*Sq*DKq];
__device__ float g_o[(size_t)Bq*Sq*Dq];       // [B,S,D]

// ---------------------------------------------------------------------------
// tf32 helpers
// ---------------------------------------------------------------------------
__device__ __forceinline__ float tf32rf(float x) {
    uint32_t r;
    asm("cvt.rna.tf32.f32 %0, %1;" : "=r"(r) : "f"(x));
    return __uint_as_float(r);
}
__device__ __forceinline__ uint32_t tf32u(float x) {
    uint32_t r;
    asm("cvt.rna.tf32.f32 %0, %1;" : "=r"(r) : "f"(x));
    return r;
}
__device__ __forceinline__ void mma_tf32(float c[4],
    uint32_t a0, uint32_t a1, uint32_t a2, uint32_t a3,
    uint32_t b0, uint32_t b1)
{
    asm volatile(
        "mma.sync.aligned.m16n8k8.row.col.f32.tf32.tf32.f32 "
        "{%0,%1,%2,%3},{%4,%5,%6,%7},{%8,%9},{%0,%1,%2,%3};"
        : "+f"(c[0]), "+f"(c[1]), "+f"(c[2]), "+f"(c[3])
        : "r"(a0), "r"(a1), "r"(a2), "r"(a3), "r"(b0), "r"(b1));
}

// ---------------------------------------------------------------------------
// tf32 GEMM: C = A @ W^T + bias (unchanged from round 4 — known good, fast)
// ---------------------------------------------------------------------------
__device__ __forceinline__ int gsw(int r, int k) {
    return r * 32 + (k ^ ((r & 3) << 3));
}

__global__ __launch_bounds__(256) void gemm_tc_kernel(
    const float* __restrict__ A, const float* __restrict__ W,
    const float* __restrict__ bias, float* __restrict__ C, int split)
{
    __shared__ float As[128 * 32];
    __shared__ float Ws[128 * 32];

    const int tid  = threadIdx.x;
    const int w    = tid >> 5;
    const int lane = tid & 31;
    const int g    = lane >> 2;
    const int t    = lane & 3;
    const int m0 = blockIdx.y * 128;
    const int n0 = blockIdx.x * 128;

    float acc[16][4];
#pragma unroll
    for (int nt = 0; nt < 16; nt++)
#pragma unroll
        for (int j = 0; j < 4; j++) acc[nt][j] = 0.f;

    const int ra = w * 16 + g;
    const int swa = (g & 3) << 3;

    for (int k0 = 0; k0 < 768; k0 += 32) {
        __syncthreads();
        const float4* A4 = (const float4*)(A + (size_t)m0 * 768 + k0);
        const float4* W4 = (const float4*)(W + (size_t)n0 * 768 + k0);
#pragma unroll
        for (int it = 0; it < 4; it++) {
            int i = tid + it * 256;
            int m = i >> 3, k4 = (i & 7) << 2;
            float4 v = A4[(size_t)m * 192 + (i & 7)];
            *(float4*)&As[gsw(m, k4)] =
                make_float4(tf32rf(v.x), tf32rf(v.y), tf32rf(v.z), tf32rf(v.w));
            float4 u = W4[(size_t)m * 192 + (i & 7)];
            *(float4*)&Ws[gsw(m, k4)] =
                make_float4(tf32rf(u.x), tf32rf(u.y), tf32rf(u.z), tf32rf(u.w));
        }
        __syncthreads();

#pragma unroll
        for (int ks = 0; ks < 4; ks++) {
            int kk = ks * 8 + 2 * t;
            float2 fa0 = *(const float2*)&As[ra * 32 + (kk ^ swa)];
            float2 fa1 = *(const float2*)&As[(ra + 8) * 32 + (kk ^ swa)];
            uint32_t a0 = __float_as_uint(fa0.x);
            uint32_t a2 = __float_as_uint(fa0.y);
            uint32_t a1 = __float_as_uint(fa1.x);
            uint32_t a3 = __float_as_uint(fa1.y);
#pragma unroll
            for (int nt = 0; nt < 16; nt++) {
                int rn = nt * 8 + g;
                float2 fb = *(const float2*)&Ws[rn * 32 + (kk ^ ((g & 3) << 3))];
                mma_tf32(acc[nt], a0, a1, a2, a3,
                         __float_as_uint(fb.x), __float_as_uint(fb.y));
            }
        }
    }

#pragma unroll
    for (int nt = 0; nt < 16; nt++) {
        int n = n0 + nt * 8 + 2 * t;
        float2 bv = *(const float2*)&bias[n];
        int ma = m0 + w * 16 + g;
        int mb = ma + 8;
        float2 v0 = make_float2(acc[nt][0] + bv.x, acc[nt][1] + bv.y);
        float2 v1 = make_float2(acc[nt][2] + bv.x, acc[nt][3] + bv.y);
        if (split) {
            int hh = n >> 6, dk = n & 63;
            int ba = ma >> 12, sa = ma & 4095;
            int bb = mb >> 12, sb = mb & 4095;
            *(float2*)&C[(((size_t)ba * Hq + hh) * Sq + sa) * DKq + dk] = v0;
            *(float2*)&C[(((size_t)bb * Hq + hh) * Sq + sb) * DKq + dk] = v1;
        } else {
            *(float2*)&C[(size_t)ma * 768 + n] = v0;
            *(float2*)&C[(size_t)mb * 768 + n] = v1;
        }
    }
}

// ---------------------------------------------------------------------------
// Flash attention tf32, register-passed P; V kept ROW-MAJOR (stride 68) and
// read as two conflict-free scalar B-frag loads (bank = 8t+g, all distinct).
// CTA: 128 q-rows, 8 warps x 16 rows; KV tile 64.
// smem: Ks[64*64] swizzled + Vs[64][68] = 33.4 KB
// ---------------------------------------------------------------------------
#define VSTR 68
__device__ __forceinline__ int ksw(int r, int k) {
    return r * 64 + (k ^ ((r & 7) << 3));
}

__global__ __launch_bounds__(256, 2) void attn_tc_kernel(
    const int* __restrict__ mask,
    const float* __restrict__ Q, const float* __restrict__ K,
    const float* __restrict__ V, float* __restrict__ O)
{
    __shared__ float Ks[64 * 64];
    __shared__ float Vs[64 * VSTR];

    const int tid  = threadIdx.x;
    const int w    = tid >> 5;
    const int lane = tid & 31;
    const int g    = lane >> 2;
    const int t    = lane & 3;

    const int qt = blockIdx.x;
    const int h  = blockIdx.y;
    const int b  = blockIdx.z;
    const size_t bh = (size_t)b * Hq + h;
    const float* Qb = Q + (bh * Sq + (size_t)qt * 128) * DKq;
    const float* Kb = K + bh * Sq * DKq;
    const float* Vb = V + bh * Sq * DKq;

    // Q A-frags in registers (pre-scaled, tf32)
    uint32_t qa[8][4];
    {
        const float* Qr0 = Qb + (size_t)(w * 16 + g) * DKq;
#pragma unroll
        for (int ks = 0; ks < 8; ks++) {
            float2 t0 = *(const float2*)&Qr0[ks * 8 + 2 * t];
            float2 t1 = *(const float2*)&Qr0[8 * DKq + ks * 8 + 2 * t];
            qa[ks][0] = tf32u(t0.x * 0.125f);
            qa[ks][2] = tf32u(t0.y * 0.125f);
            qa[ks][1] = tf32u(t1.x * 0.125f);
            qa[ks][3] = tf32u(t1.y * 0.125f);
        }
    }

    float o[8][4];
#pragma unroll
    for (int nt = 0; nt < 8; nt++)
#pragma unroll
        for (int j = 0; j < 4; j++) o[nt][j] = 0.f;
    float m0 = -1e30f, m1 = -1e30f, l0 = 0.f, l1 = 0.f;

    const int row0 = qt * 128 + w * 16 + g;
    const int2* mrow0 = (const int2*)(mask + ((size_t)b * Sq + row0) * Sq);
    const int2* mrow1 = (const int2*)(mask + ((size_t)b * Sq + row0 + 8) * Sq);

    for (int kt = 0; kt < Sq / 64; kt++) {
        __syncthreads();
        {
            const float4* K4 = (const float4*)(Kb + (size_t)kt * 64 * DKq);
            const float4* V4 = (const float4*)(Vb + (size_t)kt * 64 * DKq);
#pragma unroll
            for (int it = 0; it < 4; it++) {
                int i = tid + it * 256;
                int r = i >> 4, k4 = (i & 15) << 2;
                float4 kk = K4[i];
                *(float4*)&Ks[ksw(r, k4)] =
                    make_float4(tf32rf(kk.x), tf32rf(kk.y),
                                tf32rf(kk.z), tf32rf(kk.w));
                float4 vv = V4[i];
                *(float4*)&Vs[r * VSTR + k4] =
                    make_float4(tf32rf(vv.x), tf32rf(vv.y),
                                tf32rf(vv.z), tf32rf(vv.w));
            }
        }
        __syncthreads();

        // ---- S = Q K^T (warp: 16 x 64)
        float cs[8][4];
#pragma unroll
        for (int nt = 0; nt < 8; nt++)
#pragma unroll
            for (int j = 0; j < 4; j++) cs[nt][j] = 0.f;

#pragma unroll
        for (int ks = 0; ks < 8; ks++) {
            int kk = ks * 8 + 2 * t;
#pragma unroll
            for (int nt = 0; nt < 8; nt++) {
                int rn = nt * 8 + g;
                float2 fb = *(const float2*)&Ks[rn * 64 + (kk ^ (g << 3))];
                mma_tf32(cs[nt], qa[ks][0], qa[ks][1], qa[ks][2], qa[ks][3],
                         __float_as_uint(fb.x), __float_as_uint(fb.y));
            }
        }

        // ---- mask
        const int mbase = kt * 32;
#pragma unroll
        for (int nt = 0; nt < 8; nt++) {
            int2 u0 = mrow0[mbase + nt * 4 + t];
            int2 u1 = mrow1[mbase + nt * 4 + t];
            cs[nt][0] = u0.x ? cs[nt][0] : NEGV;
            cs[nt][1] = u0.y ? cs[nt][1] : NEGV;
            cs[nt][2] = u1.x ? cs[nt][2] : NEGV;
            cs[nt][3] = u1.y ? cs[nt][3] : NEGV;
        }

        // ---- online softmax (rows g and g+8)
        float mx0 = NEGV, mx1 = NEGV;
#pragma unroll
        for (int nt = 0; nt < 8; nt++) {
            mx0 = fmaxf(mx0, fmaxf(cs[nt][0], cs[nt][1]));
            mx1 = fmaxf(mx1, fmaxf(cs[nt][2], cs[nt][3]));
        }
        mx0 = fmaxf(mx0, __shfl_xor_sync(0xffffffffu, mx0, 1));
        mx0 = fmaxf(mx0, __shfl_xor_sync(0xffffffffu, mx0, 2));
        mx1 = fmaxf(mx1, __shfl_xor_sync(0xffffffffu, mx1, 1));
        mx1 = fmaxf(mx1, __shfl_xor_sync(0xffffffffu, mx1, 2));
        float mn0 = fmaxf(m0, mx0), mn1 = fmaxf(m1, mx1);
        float al0 = __expf(m0 - mn0), al1 = __expf(m1 - mn1);
        m0 = mn0; m1 = mn1;

        float s0 = 0.f, s1 = 0.f;
#pragma unroll
        for (int nt = 0; nt < 8; nt++) {
            float p00 = __expf(cs[nt][0] - mn0);
            float p01 = __expf(cs[nt][1] - mn0);
            float p10 = __expf(cs[nt][2] - mn1);
            float p11 = __expf(cs[nt][3] - mn1);
            s0 += p00 + p01;
            s1 += p10 + p11;
            cs[nt][0] = __uint_as_float(tf32u(p00));
            cs[nt][1] = __uint_as_float(tf32u(p01));
            cs[nt][2] = __uint_as_float(tf32u(p10));
            cs[nt][3] = __uint_as_float(tf32u(p11));
        }
        s0 += __shfl_xor_sync(0xffffffffu, s0, 1);
        s0 += __shfl_xor_sync(0xffffffffu, s0, 2);
        s1 += __shfl_xor_sync(0xffffffffu, s1, 1);
        s1 += __shfl_xor_sync(0xffffffffu, s1, 2);
        l0 = l0 * al0 + s0;
        l1 = l1 * al1 + s1;
#pragma unroll
        for (int nt = 0; nt < 8; nt++) {
            o[nt][0] *= al0; o[nt][1] *= al0;
            o[nt][2] *= al1; o[nt][3] *= al1;
        }

        // ---- O += P V  (A = register-passed P; B = scalar loads from
        //      row-major Vs; bank = 8t+g -> conflict-free)
#pragma unroll
        for (int s = 0; s < 8; s++) {
            uint32_t a0 = __float_as_uint(cs[s][0]);
            uint32_t a2 = __float_as_uint(cs[s][1]);
            uint32_t a1 = __float_as_uint(cs[s][2]);
            uint32_t a3 = __float_as_uint(cs[s][3]);
            const float* vrow = &Vs[(s * 8 + 2 * t) * VSTR];
#pragma unroll
            for (int nt = 0; nt < 8; nt++) {
                uint32_t b0 = __float_as_uint(vrow[nt * 8 + g]);
                uint32_t b1 = __float_as_uint(vrow[VSTR + nt * 8 + g]);
                mma_tf32(o[nt], a0, a1, a2, a3, b0, b1);
            }
        }
    }

    // ---- epilogue
    const float inv0 = 1.0f / l0, inv1 = 1.0f / l1;
    float* op0 = O + ((size_t)b * Sq + row0) * Dq + h * DKq;
    float* op1 = O + ((size_t)b * Sq + row0 + 8) * Dq + h * DKq;
#pragma unroll
    for (int nt = 0; nt < 8; nt++) {
        *(float2*)&op0[nt * 8 + 2 * t] =
            make_float2(o[nt][0] * inv0, o[nt][1] * inv0);
        *(float2*)&op1[nt * 8 + 2 * t] =
            make_float2(o[nt][2] * inv1, o[nt][3] * inv1);
    }
}

// ---------------------------------------------------------------------------
extern "C" void kernel_launch(void* const* d_in, const int* in_sizes, int n_in,
                              void* d_out, int out_size)
{
    const float* x    = (const float*)d_in[0];
    const int*   mask = (const int*)  d_in[1];
    const float* Wqp  = (const float*)d_in[2];
    const float* bqp  = (const float*)d_in[3];
    const float* Wkp  = (const float*)d_in[4];
    const float* bkp  = (const float*)d_in[5];
    const float* Wvp  = (const float*)d_in[6];
    const float* bvp  = (const float*)d_in[7];
    const float* Wop  = (const float*)d_in[8];
    const float* bop  = (const float*)d_in[9];
    float* out = (float*)d_out;

    float *qp, *kp, *vp, *op;
    cudaGetSymbolAddress((void**)&qp, g_q);
    cudaGetSymbolAddress((void**)&kp, g_k);
    cudaGetSymbolAddress((void**)&vp, g_v);
    cudaGetSymbolAddress((void**)&op, g_o);

    dim3 gg(768 / 128, Mrows / 128);   // (6, 64)

    gemm_tc_kernel<<<gg, 256>>>(x, Wqp, bqp, qp, 1);
    gemm_tc_kernel<<<gg, 256>>>(x, Wkp, bkp, kp, 1);
    gemm_tc_kernel<<<gg, 256>>>(x, Wvp, bvp, vp, 1);

    attn_tc_kernel<<<dim3(Sq / 128, Hq, Bq), 256>>>(mask, qp, kp, vp, op);

    gemm_tc_kernel<<<gg, 256>>>(op, Wop, bop, out, 0);
}

// round 6
// speedup vs baseline: 11.3037x; 1.3672x over previous
#include <cuda_runtime.h>
#include <cuda_bf16.h>
#include <cstdint>

// Problem constants
#define Bq   2
#define Sq   4096
#define Dq   768
#define Hq   12
#define DKq  64
#define Mrows (Bq*Sq)        // 8192
#define NEGV -1e9f

// Scratch (device globals: allocation-free rule)
__device__ float g_q[(size_t)Bq*Hq*Sq*DKq];   // [B,H,S,DK]
__device__ float g_k[(size_t)Bq*Hq*Sq*DKq];
__device__ float g_v[(size_t)Bq*Hq*Sq*DKq];
__device__ float g_o[(size_t)Bq*Sq*Dq];       // [B,S,D]

// ---------------------------------------------------------------------------
// helpers
// ---------------------------------------------------------------------------
__device__ __forceinline__ float tf32rf(float x) {
    uint32_t r;
    asm("cvt.rna.tf32.f32 %0, %1;" : "=r"(r) : "f"(x));
    return __uint_as_float(r);
}
__device__ __forceinline__ void mma_tf32(float c[4],
    uint32_t a0, uint32_t a1, uint32_t a2, uint32_t a3,
    uint32_t b0, uint32_t b1)
{
    asm volatile(
        "mma.sync.aligned.m16n8k8.row.col.f32.tf32.tf32.f32 "
        "{%0,%1,%2,%3},{%4,%5,%6,%7},{%8,%9},{%0,%1,%2,%3};"
        : "+f"(c[0]), "+f"(c[1]), "+f"(c[2]), "+f"(c[3])
        : "r"(a0), "r"(a1), "r"(a2), "r"(a3), "r"(b0), "r"(b1));
}
// pack two f32 -> bf16x2 (lo = first arg)
__device__ __forceinline__ uint32_t bf16x2(float lo, float hi) {
    uint32_t r;
    asm("cvt.rn.bf16x2.f32 %0, %1, %2;" : "=r"(r) : "f"(hi), "f"(lo));
    return r;
}
__device__ __forceinline__ void mma_bf16(float c[4],
    uint32_t a0, uint32_t a1, uint32_t a2, uint32_t a3,
    uint32_t b0, uint32_t b1)
{
    asm volatile(
        "mma.sync.aligned.m16n8k16.row.col.f32.bf16.bf16.f32 "
        "{%0,%1,%2,%3},{%4,%5,%6,%7},{%8,%9},{%0,%1,%2,%3};"
        : "+f"(c[0]), "+f"(c[1]), "+f"(c[2]), "+f"(c[3])
        : "r"(a0), "r"(a1), "r"(a2), "r"(a3), "r"(b0), "r"(b1));
}

// ---------------------------------------------------------------------------
// tf32 GEMM: C = A @ W^T + bias (unchanged — known good)
// ---------------------------------------------------------------------------
__device__ __forceinline__ int gsw(int r, int k) {
    return r * 32 + (k ^ ((r & 3) << 3));
}

__global__ __launch_bounds__(256) void gemm_tc_kernel(
    const float* __restrict__ A, const float* __restrict__ W,
    const float* __restrict__ bias, float* __restrict__ C, int split)
{
    __shared__ float As[128 * 32];
    __shared__ float Ws[128 * 32];

    const int tid  = threadIdx.x;
    const int w    = tid >> 5;
    const int lane = tid & 31;
    const int g    = lane >> 2;
    const int t    = lane & 3;
    const int m0 = blockIdx.y * 128;
    const int n0 = blockIdx.x * 128;

    float acc[16][4];
#pragma unroll
    for (int nt = 0; nt < 16; nt++)
#pragma unroll
        for (int j = 0; j < 4; j++) acc[nt][j] = 0.f;

    const int ra = w * 16 + g;
    const int swa = (g & 3) << 3;

    for (int k0 = 0; k0 < 768; k0 += 32) {
        __syncthreads();
        const float4* A4 = (const float4*)(A + (size_t)m0 * 768 + k0);
        const float4* W4 = (const float4*)(W + (size_t)n0 * 768 + k0);
#pragma unroll
        for (int it = 0; it < 4; it++) {
            int i = tid + it * 256;
            int m = i >> 3, k4 = (i & 7) << 2;
            float4 v = A4[(size_t)m * 192 + (i & 7)];
            *(float4*)&As[gsw(m, k4)] =
                make_float4(tf32rf(v.x), tf32rf(v.y), tf32rf(v.z), tf32rf(v.w));
            float4 u = W4[(size_t)m * 192 + (i & 7)];
            *(float4*)&Ws[gsw(m, k4)] =
                make_float4(tf32rf(u.x), tf32rf(u.y), tf32rf(u.z), tf32rf(u.w));
        }
        __syncthreads();

#pragma unroll
        for (int ks = 0; ks < 4; ks++) {
            int kk = ks * 8 + 2 * t;
            float2 fa0 = *(const float2*)&As[ra * 32 + (kk ^ swa)];
            float2 fa1 = *(const float2*)&As[(ra + 8) * 32 + (kk ^ swa)];
            uint32_t a0 = __float_as_uint(fa0.x);
            uint32_t a2 = __float_as_uint(fa0.y);
            uint32_t a1 = __float_as_uint(fa1.x);
            uint32_t a3 = __float_as_uint(fa1.y);
#pragma unroll
            for (int nt = 0; nt < 16; nt++) {
                int rn = nt * 8 + g;
                float2 fb = *(const float2*)&Ws[rn * 32 + (kk ^ ((g & 3) << 3))];
                mma_tf32(acc[nt], a0, a1, a2, a3,
                         __float_as_uint(fb.x), __float_as_uint(fb.y));
            }
        }
    }

#pragma unroll
    for (int nt = 0; nt < 16; nt++) {
        int n = n0 + nt * 8 + 2 * t;
        float2 bv = *(const float2*)&bias[n];
        int ma = m0 + w * 16 + g;
        int mb = ma + 8;
        float2 v0 = make_float2(acc[nt][0] + bv.x, acc[nt][1] + bv.y);
        float2 v1 = make_float2(acc[nt][2] + bv.x, acc[nt][3] + bv.y);
        if (split) {
            int hh = n >> 6, dk = n & 63;
            int ba = ma >> 12, sa = ma & 4095;
            int bb = mb >> 12, sb = mb & 4095;
            *(float2*)&C[(((size_t)ba * Hq + hh) * Sq + sa) * DKq + dk] = v0;
            *(float2*)&C[(((size_t)bb * Hq + hh) * Sq + sb) * DKq + dk] = v1;
        } else {
            *(float2*)&C[(size_t)ma * 768 + n] = v0;
            *(float2*)&C[(size_t)mb * 768 + n] = v1;
        }
    }
}

// ---------------------------------------------------------------------------
// Flash attention, bf16 m16n8k16, register-passed P.
// K in smem row-major bf16 [64 rows][72] (u32 stride 36): B-frag = 1 LDS.32,
//   bank = 4g+t+8ks (conflict-free).
// V packed at fill: VsP[d][kvp] u32 = {V[2kvp][d], V[2kvp+1][d]} bf16 pair,
//   stride 36 u32: B-frag bank = 4g+t (conflict-free).
// CTA: 128 q-rows, 8 warps x 16 rows; KV tile 64.
// ---------------------------------------------------------------------------
__global__ __launch_bounds__(256, 2) void attn_tc_kernel(
    const int* __restrict__ mask,
    const float* __restrict__ Q, const float* __restrict__ K,
    const float* __restrict__ V, float* __restrict__ O)
{
    __shared__ __align__(16) uint32_t KsP[64 * 36];
    __shared__ __align__(16) uint32_t VsP[64 * 36];

    const int tid  = threadIdx.x;
    const int w    = tid >> 5;
    const int lane = tid & 31;
    const int g    = lane >> 2;
    const int t    = lane & 3;

    const int qt = blockIdx.x;
    const int h  = blockIdx.y;
    const int b  = blockIdx.z;
    const size_t bh = (size_t)b * Hq + h;
    const float* Qb = Q + (bh * Sq + (size_t)qt * 128) * DKq;
    const float* Kb = K + bh * Sq * DKq;
    const float* Vb = V + bh * Sq * DKq;

    // Q A-frags in registers (pre-scaled, bf16 pairs)
    uint32_t qa[4][4];
    {
        const float* Qr0 = Qb + (size_t)(w * 16 + g) * DKq;
        const float* Qr1 = Qr0 + 8 * DKq;
#pragma unroll
        for (int ks = 0; ks < 4; ks++) {
            float2 x0 = *(const float2*)&Qr0[ks * 16 + 2 * t];
            float2 x1 = *(const float2*)&Qr1[ks * 16 + 2 * t];
            float2 x2 = *(const float2*)&Qr0[ks * 16 + 8 + 2 * t];
            float2 x3 = *(const float2*)&Qr1[ks * 16 + 8 + 2 * t];
            qa[ks][0] = bf16x2(x0.x * 0.125f, x0.y * 0.125f);
            qa[ks][1] = bf16x2(x1.x * 0.125f, x1.y * 0.125f);
            qa[ks][2] = bf16x2(x2.x * 0.125f, x2.y * 0.125f);
            qa[ks][3] = bf16x2(x3.x * 0.125f, x3.y * 0.125f);
        }
    }

    float o[8][4];
#pragma unroll
    for (int nt = 0; nt < 8; nt++)
#pragma unroll
        for (int j = 0; j < 4; j++) o[nt][j] = 0.f;
    float m0 = -1e30f, m1 = -1e30f, l0 = 0.f, l1 = 0.f;

    const int row0 = qt * 128 + w * 16 + g;
    const int2* mrow0 = (const int2*)(mask + ((size_t)b * Sq + row0) * Sq);
    const int2* mrow1 = (const int2*)(mask + ((size_t)b * Sq + row0 + 8) * Sq);

    for (int kt = 0; kt < Sq / 64; kt++) {
        __syncthreads();
        {
            // K: row-major bf16 [64][72]; fill from float4, 2-way max
            const float4* K4 = (const float4*)(Kb + (size_t)kt * 64 * DKq);
#pragma unroll
            for (int it = 0; it < 4; it++) {
                int i = tid + it * 256;       // 1024 float4-quads
                int r = i >> 4, q = i & 15;
                float4 kk = K4[r * 16 + q];
                *(uint2*)&KsP[r * 36 + q * 2] =
                    make_uint2(bf16x2(kk.x, kk.y), bf16x2(kk.z, kk.w));
            }
            // V: packed kv-pairs: VsP[d*36+kvp] = {V[2kvp][d], V[2kvp+1][d]}
            const float* Vt = Vb + (size_t)kt * 64 * DKq;
#pragma unroll
            for (int it = 0; it < 8; it++) {
                int i = tid + it * 256;       // 2048 pairs
                int d = i & 63, kvp = i >> 6;
                float va = Vt[(2 * kvp) * DKq + d];
                float vb = Vt[(2 * kvp + 1) * DKq + d];
                VsP[d * 36 + kvp] = bf16x2(va, vb);
            }
        }
        __syncthreads();

        // ---- S = Q K^T (warp: 16 x 64), bf16 k16
        float cs[8][4];
#pragma unroll
        for (int nt = 0; nt < 8; nt++)
#pragma unroll
            for (int j = 0; j < 4; j++) cs[nt][j] = 0.f;

#pragma unroll
        for (int ks = 0; ks < 4; ks++) {
#pragma unroll
            for (int nt = 0; nt < 8; nt++) {
                const uint32_t* kp = &KsP[(nt * 8 + g) * 36 + ks * 8 + t];
                mma_bf16(cs[nt], qa[ks][0], qa[ks][1], qa[ks][2], qa[ks][3],
                         kp[0], kp[4]);
            }
        }

        // ---- mask
        const int mbase = kt * 32;
#pragma unroll
        for (int nt = 0; nt < 8; nt++) {
            int2 u0 = mrow0[mbase + nt * 4 + t];
            int2 u1 = mrow1[mbase + nt * 4 + t];
            cs[nt][0] = u0.x ? cs[nt][0] : NEGV;
            cs[nt][1] = u0.y ? cs[nt][1] : NEGV;
            cs[nt][2] = u1.x ? cs[nt][2] : NEGV;
            cs[nt][3] = u1.y ? cs[nt][3] : NEGV;
        }

        // ---- online softmax (rows g and g+8)
        float mx0 = NEGV, mx1 = NEGV;
#pragma unroll
        for (int nt = 0; nt < 8; nt++) {
            mx0 = fmaxf(mx0, fmaxf(cs[nt][0], cs[nt][1]));
            mx1 = fmaxf(mx1, fmaxf(cs[nt][2], cs[nt][3]));
        }
        mx0 = fmaxf(mx0, __shfl_xor_sync(0xffffffffu, mx0, 1));
        mx0 = fmaxf(mx0, __shfl_xor_sync(0xffffffffu, mx0, 2));
        mx1 = fmaxf(mx1, __shfl_xor_sync(0xffffffffu, mx1, 1));
        mx1 = fmaxf(mx1, __shfl_xor_sync(0xffffffffu, mx1, 2));
        float mn0 = fmaxf(m0, mx0), mn1 = fmaxf(m1, mx1);
        float al0 = __expf(m0 - mn0), al1 = __expf(m1 - mn1);
        m0 = mn0; m1 = mn1;

        uint32_t pA0[8], pA1[8];   // P A-frags: row g pairs, row g+8 pairs
        float s0 = 0.f, s1 = 0.f;
#pragma unroll
        for (int nt = 0; nt < 8; nt++) {
            float p00 = __expf(cs[nt][0] - mn0);
            float p01 = __expf(cs[nt][1] - mn0);
            float p10 = __expf(cs[nt][2] - mn1);
            float p11 = __expf(cs[nt][3] - mn1);
            s0 += p00 + p01;
            s1 += p10 + p11;
            pA0[nt] = bf16x2(p00, p01);
            pA1[nt] = bf16x2(p10, p11);
        }
        s0 += __shfl_xor_sync(0xffffffffu, s0, 1);
        s0 += __shfl_xor_sync(0xffffffffu, s0, 2);
        s1 += __shfl_xor_sync(0xffffffffu, s1, 1);
        s1 += __shfl_xor_sync(0xffffffffu, s1, 2);
        l0 = l0 * al0 + s0;
        l1 = l1 * al1 + s1;
#pragma unroll
        for (int nt = 0; nt < 8; nt++) {
            o[nt][0] *= al0; o[nt][1] *= al0;
            o[nt][2] *= al1; o[nt][3] *= al1;
        }

        // ---- O += P V  (A = register-passed bf16 P; B from packed VsP)
#pragma unroll
        for (int j = 0; j < 4; j++) {
            uint32_t a0 = pA0[2 * j];
            uint32_t a1 = pA1[2 * j];
            uint32_t a2 = pA0[2 * j + 1];
            uint32_t a3 = pA1[2 * j + 1];
#pragma unroll
            for (int nt = 0; nt < 8; nt++) {
                const uint32_t* vp = &VsP[(nt * 8 + g) * 36 + 8 * j + t];
                mma_bf16(o[nt], a0, a1, a2, a3, vp[0], vp[4]);
            }
        }
    }

    // ---- epilogue
    const float inv0 = 1.0f / l0, inv1 = 1.0f / l1;
    float* op0 = O + ((size_t)b * Sq + row0) * Dq + h * DKq;
    float* op1 = O + ((size_t)b * Sq + row0 + 8) * Dq + h * DKq;
#pragma unroll
    for (int nt = 0; nt < 8; nt++) {
        *(float2*)&op0[nt * 8 + 2 * t] =
            make_float2(o[nt][0] * inv0, o[nt][1] * inv0);
        *(float2*)&op1[nt * 8 + 2 * t] =
            make_float2(o[nt][2] * inv1, o[nt][3] * inv1);
    }
}

// ---------------------------------------------------------------------------
extern "C" void kernel_launch(void* const* d_in, const int* in_sizes, int n_in,
                              void* d_out, int out_size)
{
    const float* x    = (const float*)d_in[0];
    const int*   mask = (const int*)  d_in[1];
    const float* Wqp  = (const float*)d_in[2];
    const float* bqp  = (const float*)d_in[3];
    const float* Wkp  = (const float*)d_in[4];
    const float* bkp  = (const float*)d_in[5];
    const float* Wvp  = (const float*)d_in[6];
    const float* bvp  = (const float*)d_in[7];
    const float* Wop  = (const float*)d_in[8];
    const float* bop  = (const float*)d_in[9];
    float* out = (float*)d_out;

    float *qp, *kp, *vp, *op;
    cudaGetSymbolAddress((void**)&qp, g_q);
    cudaGetSymbolAddress((void**)&kp, g_k);
    cudaGetSymbolAddress((void**)&vp, g_v);
    cudaGetSymbolAddress((void**)&op, g_o);

    dim3 gg(768 / 128, Mrows / 128);   // (6, 64)

    gemm_tc_kernel<<<gg, 256>>>(x, Wqp, bqp, qp, 1);
    gemm_tc_kernel<<<gg, 256>>>(x, Wkp, bkp, kp, 1);
    gemm_tc_kernel<<<gg, 256>>>(x, Wvp, bvp, vp, 1);

    attn_tc_kernel<<<dim3(Sq / 128, Hq, Bq), 256>>>(mask, qp, kp, vp, op);

    gemm_tc_kernel<<<gg, 256>>>(op, Wop, bop, out, 0);
}

// round 8
// speedup vs baseline: 12.8461x; 1.1364x over previous
#include <cuda_runtime.h>
#include <cuda_bf16.h>
#include <cstdint>

// Problem constants
#define Bq   2
#define Sq   4096
#define Dq   768
#define Hq   12
#define DKq  64
#define Mrows (Bq*Sq)        // 8192
#define NEGV -1e9f

// Scratch (device globals: allocation-free rule)
__device__ __nv_bfloat16 g_qb[(size_t)Bq*Hq*Sq*DKq];   // [B,H,S,DK], pre-scaled
__device__ __nv_bfloat16 g_kb[(size_t)Bq*Hq*Sq*DKq];   // [B,H,S,DK]
__device__ __nv_bfloat16 g_vt[(size_t)Bq*Hq*DKq*Sq];   // [B,H,DK,S] (transposed)
__device__ float         g_o [(size_t)Bq*Sq*Dq];       // [B,S,D]

// ---------------------------------------------------------------------------
// helpers
// ---------------------------------------------------------------------------
__device__ __forceinline__ float tf32rf(float x) {
    uint32_t r;
    asm("cvt.rna.tf32.f32 %0, %1;" : "=r"(r) : "f"(x));
    return __uint_as_float(r);
}
__device__ __forceinline__ void mma_tf32(float c[4],
    uint32_t a0, uint32_t a1, uint32_t a2, uint32_t a3,
    uint32_t b0, uint32_t b1)
{
    asm volatile(
        "mma.sync.aligned.m16n8k8.row.col.f32.tf32.tf32.f32 "
        "{%0,%1,%2,%3},{%4,%5,%6,%7},{%8,%9},{%0,%1,%2,%3};"
        : "+f"(c[0]), "+f"(c[1]), "+f"(c[2]), "+f"(c[3])
        : "r"(a0), "r"(a1), "r"(a2), "r"(a3), "r"(b0), "r"(b1));
}
__device__ __forceinline__ uint32_t bf16x2(float lo, float hi) {
    uint32_t r;
    asm("cvt.rn.bf16x2.f32 %0, %1, %2;" : "=r"(r) : "f"(hi), "f"(lo));
    return r;
}
__device__ __forceinline__ void mma_bf16(float c[4],
    uint32_t a0, uint32_t a1, uint32_t a2, uint32_t a3,
    uint32_t b0, uint32_t b1)
{
    asm volatile(
        "mma.sync.aligned.m16n8k16.row.col.f32.bf16.bf16.f32 "
        "{%0,%1,%2,%3},{%4,%5,%6,%7},{%8,%9},{%0,%1,%2,%3};"
        : "+f"(c[0]), "+f"(c[1]), "+f"(c[2]), "+f"(c[3])
        : "r"(a0), "r"(a1), "r"(a2), "r"(a3), "r"(b0), "r"(b1));
}
__device__ __forceinline__ void cpa16(uint32_t dst_smem, const void* src) {
    asm volatile("cp.async.cg.shared.global [%0], [%1], 16;"
                 :: "r"(dst_smem), "l"(src));
}

// ---------------------------------------------------------------------------
// tf32 GEMM: C = A @ W^T + bias.
// mode 0: fp32 flat [M,768]
// mode 1: bf16 split [B,H,S,DK], values scaled by `scale`
// mode 2: bf16 transposed split [B,H,DK,S]
// ---------------------------------------------------------------------------
__device__ __forceinline__ int gsw(int r, int k) {
    return r * 32 + (k ^ ((r & 3) << 3));
}

__global__ __launch_bounds__(256) void gemm_tc_kernel(
    const float* __restrict__ A, const float* __restrict__ W,
    const float* __restrict__ bias, void* __restrict__ Cv,
    int mode, float scale)
{
    __shared__ float As[128 * 32];
    __shared__ float Ws[128 * 32];

    const int tid  = threadIdx.x;
    const int w    = tid >> 5;
    const int lane = tid & 31;
    const int g    = lane >> 2;
    const int t    = lane & 3;
    const int m0 = blockIdx.y * 128;
    const int n0 = blockIdx.x * 128;

    float acc[16][4];
#pragma unroll
    for (int nt = 0; nt < 16; nt++)
#pragma unroll
        for (int j = 0; j < 4; j++) acc[nt][j] = 0.f;

    const int ra = w * 16 + g;
    const int swa = (g & 3) << 3;

    for (int k0 = 0; k0 < 768; k0 += 32) {
        __syncthreads();
        const float4* A4 = (const float4*)(A + (size_t)m0 * 768 + k0);
        const float4* W4 = (const float4*)(W + (size_t)n0 * 768 + k0);
#pragma unroll
        for (int it = 0; it < 4; it++) {
            int i = tid + it * 256;
            int m = i >> 3, k4 = (i & 7) << 2;
            float4 v = A4[(size_t)m * 192 + (i & 7)];
            *(float4*)&As[gsw(m, k4)] =
                make_float4(tf32rf(v.x), tf32rf(v.y), tf32rf(v.z), tf32rf(v.w));
            float4 u = W4[(size_t)m * 192 + (i & 7)];
            *(float4*)&Ws[gsw(m, k4)] =
                make_float4(tf32rf(u.x), tf32rf(u.y), tf32rf(u.z), tf32rf(u.w));
        }
        __syncthreads();

#pragma unroll
        for (int ks = 0; ks < 4; ks++) {
            int kk = ks * 8 + 2 * t;
            float2 fa0 = *(const float2*)&As[ra * 32 + (kk ^ swa)];
            float2 fa1 = *(const float2*)&As[(ra + 8) * 32 + (kk ^ swa)];
            uint32_t a0 = __float_as_uint(fa0.x);
            uint32_t a2 = __float_as_uint(fa0.y);
            uint32_t a1 = __float_as_uint(fa1.x);
            uint32_t a3 = __float_as_uint(fa1.y);
#pragma unroll
            for (int nt = 0; nt < 16; nt++) {
                int rn = nt * 8 + g;
                float2 fb = *(const float2*)&Ws[rn * 32 + (kk ^ ((g & 3) << 3))];
                mma_tf32(acc[nt], a0, a1, a2, a3,
                         __float_as_uint(fb.x), __float_as_uint(fb.y));
            }
        }
    }

#pragma unroll
    for (int nt = 0; nt < 16; nt++) {
        int n = n0 + nt * 8 + 2 * t;
        float2 bv = *(const float2*)&bias[n];
        int ma = m0 + w * 16 + g;
        int mb = ma + 8;
        float c00 = acc[nt][0] + bv.x, c01 = acc[nt][1] + bv.y;
        float c10 = acc[nt][2] + bv.x, c11 = acc[nt][3] + bv.y;
        if (mode == 0) {
            float* C = (float*)Cv;
            *(float2*)&C[(size_t)ma * 768 + n] = make_float2(c00, c01);
            *(float2*)&C[(size_t)mb * 768 + n] = make_float2(c10, c11);
        } else {
            int hh = n >> 6, dk = n & 63;
            int ba = ma >> 12, sa = ma & 4095;
            int bb = mb >> 12, sb = mb & 4095;
            __nv_bfloat16* C16 = (__nv_bfloat16*)Cv;
            if (mode == 1) {
                uint32_t p0 = bf16x2(c00 * scale, c01 * scale);
                uint32_t p1 = bf16x2(c10 * scale, c11 * scale);
                *(uint32_t*)&C16[(((size_t)ba * Hq + hh) * Sq + sa) * DKq + dk] = p0;
                *(uint32_t*)&C16[(((size_t)bb * Hq + hh) * Sq + sb) * DKq + dk] = p1;
            } else {
                // V^T: [B,H,DK,S]
                size_t base_a = (((size_t)ba * Hq + hh) * DKq + dk) * Sq;
                size_t base_b = (((size_t)bb * Hq + hh) * DKq + dk) * Sq;
                C16[base_a + sa]      = __float2bfloat16(c00);
                C16[base_a + Sq + sa] = __float2bfloat16(c01);
                C16[base_b + sb]      = __float2bfloat16(c10);
                C16[base_b + Sq + sb] = __float2bfloat16(c11);
            }
        }
    }
}

// ---------------------------------------------------------------------------
// Flash attention, bf16 m16n8k16, register-passed P, cp.async double-buffered
// K/V tiles (bf16 produced by the projection GEMMs; V pre-transposed).
// smem row = 36 u32 (144 B): data in u32 [0,32), 16 B chunks at col*4.
// CTA: 128 q-rows, 8 warps x 16 rows; KV tile 64.
// ---------------------------------------------------------------------------
__global__ __launch_bounds__(256, 2) void attn_tc_kernel(
    const int* __restrict__ mask,
    const __nv_bfloat16* __restrict__ Q, const __nv_bfloat16* __restrict__ K,
    const __nv_bfloat16* __restrict__ VT, float* __restrict__ O)
{
    __shared__ __align__(16) uint32_t KsP[2][64 * 36];
    __shared__ __align__(16) uint32_t VsP[2][64 * 36];

    const int tid  = threadIdx.x;
    const int w    = tid >> 5;
    const int lane = tid & 31;
    const int g    = lane >> 2;
    const int t    = lane & 3;

    const int qt = blockIdx.x;
    const int h  = blockIdx.y;
    const int b  = blockIdx.z;
    const size_t bh = (size_t)b * Hq + h;
    const __nv_bfloat16* Kb  = K  + bh * Sq * DKq;
    const __nv_bfloat16* VTb = VT + bh * DKq * Sq;

    // Q A-frags straight from bf16 gmem (already scaled by 1/8)
    uint32_t qa[4][4];
    {
        const uint32_t* Qu0 = (const uint32_t*)
            (Q + (bh * Sq + (size_t)qt * 128 + w * 16 + g) * DKq);
        const uint32_t* Qu1 = Qu0 + 8 * (DKq / 2);
#pragma unroll
        for (int ks = 0; ks < 4; ks++) {
            qa[ks][0] = Qu0[ks * 8 + t];
            qa[ks][1] = Qu1[ks * 8 + t];
            qa[ks][2] = Qu0[ks * 8 + 4 + t];
            qa[ks][3] = Qu1[ks * 8 + 4 + t];
        }
    }

    uint32_t ks_base[2], vs_base[2];
    ks_base[0] = (uint32_t)__cvta_generic_to_shared(&KsP[0][0]);
    ks_base[1] = (uint32_t)__cvta_generic_to_shared(&KsP[1][0]);
    vs_base[0] = (uint32_t)__cvta_generic_to_shared(&VsP[0][0]);
    vs_base[1] = (uint32_t)__cvta_generic_to_shared(&VsP[1][0]);

    // async copy of one KV tile into buffer `buf`
    // 64 rows x 8 chunks of 16 B; dst u32 offset = r*36 + col*4 (16B-aligned)
    auto copyKV = [&](int buf, int kt) {
#pragma unroll
        for (int it = 0; it < 2; it++) {
            int c = tid + it * 256;           // 512 chunks each
            int r = c >> 3, col = c & 7;
            cpa16(ks_base[buf] + (uint32_t)(r * 36 + col * 4) * 4,
                  Kb + (size_t)kt * 64 * DKq + r * DKq + col * 8);
            cpa16(vs_base[buf] + (uint32_t)(r * 36 + col * 4) * 4,
                  VTb + (size_t)r * Sq + kt * 64 + col * 8);
        }
    };

    float o[8][4];
#pragma unroll
    for (int nt = 0; nt < 8; nt++)
#pragma unroll
        for (int j = 0; j < 4; j++) o[nt][j] = 0.f;
    float m0 = -1e30f, m1 = -1e30f, lp0 = 0.f, lp1 = 0.f;

    const int row0 = qt * 128 + w * 16 + g;
    const int2* mrow0 = (const int2*)(mask + ((size_t)b * Sq + row0) * Sq);
    const int2* mrow1 = (const int2*)(mask + ((size_t)b * Sq + row0 + 8) * Sq);

    const int T = Sq / 64;
    copyKV(0, 0);
    asm volatile("cp.async.commit_group;" ::: "memory");

    for (int kt = 0; kt < T; kt++) {
        const int buf = kt & 1;
        __syncthreads();   // all warps done reading buf^1 (iter kt-1)
        if (kt + 1 < T) {
            copyKV(buf ^ 1, kt + 1);
            asm volatile("cp.async.commit_group;" ::: "memory");
            asm volatile("cp.async.wait_group 1;" ::: "memory");
        } else {
            asm volatile("cp.async.wait_group 0;" ::: "memory");
        }
        __syncthreads();   // tile kt visible to all

        const uint32_t* Ksb = &KsP[buf][0];
        const uint32_t* Vsb = &VsP[buf][0];

        // ---- S = Q K^T (warp: 16 x 64), bf16 k16
        float cs[8][4];
#pragma unroll
        for (int nt = 0; nt < 8; nt++)
#pragma unroll
            for (int j = 0; j < 4; j++) cs[nt][j] = 0.f;

#pragma unroll
        for (int ks = 0; ks < 4; ks++) {
#pragma unroll
            for (int nt = 0; nt < 8; nt++) {
                const uint32_t* kp = &Ksb[(nt * 8 + g) * 36 + ks * 8 + t];
                mma_bf16(cs[nt], qa[ks][0], qa[ks][1], qa[ks][2], qa[ks][3],
                         kp[0], kp[4]);
            }
        }

        // ---- mask
        const int mbase = kt * 32;
#pragma unroll
        for (int nt = 0; nt < 8; nt++) {
            int2 u0 = mrow0[mbase + nt * 4 + t];
            int2 u1 = mrow1[mbase + nt * 4 + t];
            cs[nt][0] = u0.x ? cs[nt][0] : NEGV;
            cs[nt][1] = u0.y ? cs[nt][1] : NEGV;
            cs[nt][2] = u1.x ? cs[nt][2] : NEGV;
            cs[nt][3] = u1.y ? cs[nt][3] : NEGV;
        }

        // ---- online softmax (rows g and g+8); per-thread partial l
        float mx0 = NEGV, mx1 = NEGV;
#pragma unroll
        for (int nt = 0; nt < 8; nt++) {
            mx0 = fmaxf(mx0, fmaxf(cs[nt][0], cs[nt][1]));
            mx1 = fmaxf(mx1, fmaxf(cs[nt][2], cs[nt][3]));
        }
        mx0 = fmaxf(mx0, __shfl_xor_sync(0xffffffffu, mx0, 1));
        mx0 = fmaxf(mx0, __shfl_xor_sync(0xffffffffu, mx0, 2));
        mx1 = fmaxf(mx1, __shfl_xor_sync(0xffffffffu, mx1, 1));
        mx1 = fmaxf(mx1, __shfl_xor_sync(0xffffffffu, mx1, 2));
        float mn0 = fmaxf(m0, mx0), mn1 = fmaxf(m1, mx1);
        float al0 = __expf(m0 - mn0), al1 = __expf(m1 - mn1);
        m0 = mn0; m1 = mn1;

        uint32_t pA0[8], pA1[8];
        float s0 = 0.f, s1 = 0.f;
#pragma unroll
        for (int nt = 0; nt < 8; nt++) {
            float p00 = __expf(cs[nt][0] - mn0);
            float p01 = __expf(cs[nt][1] - mn0);
            float p10 = __expf(cs[nt][2] - mn1);
            float p11 = __expf(cs[nt][3] - mn1);
            s0 += p00 + p01;
            s1 += p10 + p11;
            pA0[nt] = bf16x2(p00, p01);
            pA1[nt] = bf16x2(p10, p11);
        }
        lp0 = lp0 * al0 + s0;     // cross-t reduction deferred to epilogue
        lp1 = lp1 * al1 + s1;
#pragma unroll
        for (int nt = 0; nt < 8; nt++) {
            o[nt][0] *= al0; o[nt][1] *= al0;
            o[nt][2] *= al1; o[nt][3] *= al1;
        }

        // ---- O += P V  (A = register-passed bf16 P; B from packed VsP)
#pragma unroll
        for (int j = 0; j < 4; j++) {
            uint32_t a0 = pA0[2 * j];
            uint32_t a1 = pA1[2 * j];
            uint32_t a2 = pA0[2 * j + 1];
            uint32_t a3 = pA1[2 * j + 1];
#pragma unroll
            for (int nt = 0; nt < 8; nt++) {
                const uint32_t* vp = &Vsb[(nt * 8 + g) * 36 + 8 * j + t];
                mma_bf16(o[nt], a0, a1, a2, a3, vp[0], vp[4]);
            }
        }
    }

    // ---- epilogue: reduce partial l across the 4 t-lanes, then write
    lp0 += __shfl_xor_sync(0xffffffffu, lp0, 1);
    lp0 += __shfl_xor_sync(0xffffffffu, lp0, 2);
    lp1 += __shfl_xor_sync(0xffffffffu, lp1, 1);
    lp1 += __shfl_xor_sync(0xffffffffu, lp1, 2);
    const float inv0 = 1.0f / lp0, inv1 = 1.0f / lp1;
    float* op0 = O + ((size_t)b * Sq + row0) * Dq + h * DKq;
    float* op1 = O + ((size_t)b * Sq + row0 + 8) * Dq + h * DKq;
#pragma unroll
    for (int nt = 0; nt < 8; nt++) {
        *(float2*)&op0[nt * 8 + 2 * t] =
            make_float2(o[nt][0] * inv0, o[nt][1] * inv0);
        *(float2*)&op1[nt * 8 + 2 * t] =
            make_float2(o[nt][2] * inv1, o[nt][3] * inv1);
    }
}

// ---------------------------------------------------------------------------
extern "C" void kernel_launch(void* const* d_in, const int* in_sizes, int n_in,
                              void* d_out, int out_size)
{
    const float* x    = (const float*)d_in[0];
    const int*   mask = (const int*)  d_in[1];
    const float* Wqp  = (const float*)d_in[2];
    const float* bqp  = (const float*)d_in[3];
    const float* Wkp  = (const float*)d_in[4];
    const float* bkp  = (const float*)d_in[5];
    const float* Wvp  = (const float*)d_in[6];
    const float* bvp  = (const float*)d_in[7];
    const float* Wop  = (const float*)d_in[8];
    const float* bop  = (const float*)d_in[9];
    float* out = (float*)d_out;

    __nv_bfloat16 *qb, *kb, *vt;
    float *op;
    cudaGetSymbolAddress((void**)&qb, g_qb);
    cudaGetSymbolAddress((void**)&kb, g_kb);
    cudaGetSymbolAddress((void**)&vt, g_vt);
    cudaGetSymbolAddress((void**)&op, g_o);

    dim3 gg(768 / 128, Mrows / 128);   // (6, 64)

    gemm_tc_kernel<<<gg, 256>>>(x, Wqp, bqp, qb, 1, 0.125f);  // Q, pre-scaled
    gemm_tc_kernel<<<gg, 256>>>(x, Wkp, bkp, kb, 1, 1.0f);    // K
    gemm_tc_kernel<<<gg, 256>>>(x, Wvp, bvp, vt, 2, 1.0f);    // V transposed

    attn_tc_kernel<<<dim3(Sq / 128, Hq, Bq), 256>>>(mask, qb, kb, vt, op);

    gemm_tc_kernel<<<gg, 256>>>(op, Wop, bop, out, 0, 1.0f);  // output proj
}

// round 9
// speedup vs baseline: 13.3958x; 1.0428x over previous
#include <cuda_runtime.h>
#include <cuda_bf16.h>
#include <cstdint>

// Problem constants
#define Bq   2
#define Sq   4096
#define Dq   768
#define Hq   12
#define DKq  64
#define Mrows (Bq*Sq)        // 8192
#define NEGV -1e9f

// Scratch (device globals: allocation-free rule)
__device__ __nv_bfloat16 g_qb[(size_t)Bq*Hq*Sq*DKq];   // [B,H,S,DK], scaled by 0.125*log2e
__device__ __nv_bfloat16 g_kb[(size_t)Bq*Hq*Sq*DKq];   // [B,H,S,DK]
__device__ __nv_bfloat16 g_vt[(size_t)Bq*Hq*DKq*Sq];   // [B,H,DK,S] (transposed)
__device__ float         g_o [(size_t)Bq*Sq*Dq];       // [B,S,D]

// ---------------------------------------------------------------------------
// helpers
// ---------------------------------------------------------------------------
__device__ __forceinline__ float tf32rf(float x) {
    uint32_t r;
    asm("cvt.rna.tf32.f32 %0, %1;" : "=r"(r) : "f"(x));
    return __uint_as_float(r);
}
__device__ __forceinline__ void mma_tf32(float c[4],
    uint32_t a0, uint32_t a1, uint32_t a2, uint32_t a3,
    uint32_t b0, uint32_t b1)
{
    asm volatile(
        "mma.sync.aligned.m16n8k8.row.col.f32.tf32.tf32.f32 "
        "{%0,%1,%2,%3},{%4,%5,%6,%7},{%8,%9},{%0,%1,%2,%3};"
        : "+f"(c[0]), "+f"(c[1]), "+f"(c[2]), "+f"(c[3])
        : "r"(a0), "r"(a1), "r"(a2), "r"(a3), "r"(b0), "r"(b1));
}
__device__ __forceinline__ uint32_t bf16x2(float lo, float hi) {
    uint32_t r;
    asm("cvt.rn.bf16x2.f32 %0, %1, %2;" : "=r"(r) : "f"(hi), "f"(lo));
    return r;
}
__device__ __forceinline__ void mma_bf16(float c[4],
    uint32_t a0, uint32_t a1, uint32_t a2, uint32_t a3,
    uint32_t b0, uint32_t b1)
{
    asm volatile(
        "mma.sync.aligned.m16n8k16.row.col.f32.bf16.bf16.f32 "
        "{%0,%1,%2,%3},{%4,%5,%6,%7},{%8,%9},{%0,%1,%2,%3};"
        : "+f"(c[0]), "+f"(c[1]), "+f"(c[2]), "+f"(c[3])
        : "r"(a0), "r"(a1), "r"(a2), "r"(a3), "r"(b0), "r"(b1));
}
__device__ __forceinline__ void cpa16(uint32_t dst_smem, const void* src) {
    asm volatile("cp.async.cg.shared.global [%0], [%1], 16;"
                 :: "r"(dst_smem), "l"(src));
}
__device__ __forceinline__ void ldsm4(uint32_t& r0, uint32_t& r1,
                                      uint32_t& r2, uint32_t& r3, uint32_t a)
{
    asm volatile("ldmatrix.sync.aligned.m8n8.x4.shared.b16 {%0,%1,%2,%3}, [%4];"
                 : "=r"(r0), "=r"(r1), "=r"(r2), "=r"(r3) : "r"(a));
}
__device__ __forceinline__ float ex2(float x) {
    float y;
    asm("ex2.approx.f32 %0, %1;" : "=f"(y) : "f"(x));
    return y;
}

// ---------------------------------------------------------------------------
// tf32 GEMM: C = A @ W^T + bias. (unchanged)
// mode 0: fp32 flat [M,768]; mode 1: bf16 split [B,H,S,DK] * scale;
// mode 2: bf16 transposed split [B,H,DK,S]
// ---------------------------------------------------------------------------
__device__ __forceinline__ int gsw(int r, int k) {
    return r * 32 + (k ^ ((r & 3) << 3));
}

__global__ __launch_bounds__(256) void gemm_tc_kernel(
    const float* __restrict__ A, const float* __restrict__ W,
    const float* __restrict__ bias, void* __restrict__ Cv,
    int mode, float scale)
{
    __shared__ float As[128 * 32];
    __shared__ float Ws[128 * 32];

    const int tid  = threadIdx.x;
    const int w    = tid >> 5;
    const int lane = tid & 31;
    const int g    = lane >> 2;
    const int t    = lane & 3;
    const int m0 = blockIdx.y * 128;
    const int n0 = blockIdx.x * 128;

    float acc[16][4];
#pragma unroll
    for (int nt = 0; nt < 16; nt++)
#pragma unroll
        for (int j = 0; j < 4; j++) acc[nt][j] = 0.f;

    const int ra = w * 16 + g;
    const int swa = (g & 3) << 3;

    for (int k0 = 0; k0 < 768; k0 += 32) {
        __syncthreads();
        const float4* A4 = (const float4*)(A + (size_t)m0 * 768 + k0);
        const float4* W4 = (const float4*)(W + (size_t)n0 * 768 + k0);
#pragma unroll
        for (int it = 0; it < 4; it++) {
            int i = tid + it * 256;
            int m = i >> 3, k4 = (i & 7) << 2;
            float4 v = A4[(size_t)m * 192 + (i & 7)];
            *(float4*)&As[gsw(m, k4)] =
                make_float4(tf32rf(v.x), tf32rf(v.y), tf32rf(v.z), tf32rf(v.w));
            float4 u = W4[(size_t)m * 192 + (i & 7)];
            *(float4*)&Ws[gsw(m, k4)] =
                make_float4(tf32rf(u.x), tf32rf(u.y), tf32rf(u.z), tf32rf(u.w));
        }
        __syncthreads();

#pragma unroll
        for (int ks = 0; ks < 4; ks++) {
            int kk = ks * 8 + 2 * t;
            float2 fa0 = *(const float2*)&As[ra * 32 + (kk ^ swa)];
            float2 fa1 = *(const float2*)&As[(ra + 8) * 32 + (kk ^ swa)];
            uint32_t a0 = __float_as_uint(fa0.x);
            uint32_t a2 = __float_as_uint(fa0.y);
            uint32_t a1 = __float_as_uint(fa1.x);
            uint32_t a3 = __float_as_uint(fa1.y);
#pragma unroll
            for (int nt = 0; nt < 16; nt++) {
                int rn = nt * 8 + g;
                float2 fb = *(const float2*)&Ws[rn * 32 + (kk ^ ((g & 3) << 3))];
                mma_tf32(acc[nt], a0, a1, a2, a3,
                         __float_as_uint(fb.x), __float_as_uint(fb.y));
            }
        }
    }

#pragma unroll
    for (int nt = 0; nt < 16; nt++) {
        int n = n0 + nt * 8 + 2 * t;
        float2 bv = *(const float2*)&bias[n];
        int ma = m0 + w * 16 + g;
        int mb = ma + 8;
        float c00 = acc[nt][0] + bv.x, c01 = acc[nt][1] + bv.y;
        float c10 = acc[nt][2] + bv.x, c11 = acc[nt][3] + bv.y;
        if (mode == 0) {
            float* C = (float*)Cv;
            *(float2*)&C[(size_t)ma * 768 + n] = make_float2(c00, c01);
            *(float2*)&C[(size_t)mb * 768 + n] = make_float2(c10, c11);
        } else {
            int hh = n >> 6, dk = n & 63;
            int ba = ma >> 12, sa = ma & 4095;
            int bb = mb >> 12, sb = mb & 4095;
            __nv_bfloat16* C16 = (__nv_bfloat16*)Cv;
            if (mode == 1) {
                uint32_t p0 = bf16x2(c00 * scale, c01 * scale);
                uint32_t p1 = bf16x2(c10 * scale, c11 * scale);
                *(uint32_t*)&C16[(((size_t)ba * Hq + hh) * Sq + sa) * DKq + dk] = p0;
                *(uint32_t*)&C16[(((size_t)bb * Hq + hh) * Sq + sb) * DKq + dk] = p1;
            } else {
                size_t base_a = (((size_t)ba * Hq + hh) * DKq + dk) * Sq;
                size_t base_b = (((size_t)bb * Hq + hh) * DKq + dk) * Sq;
                C16[base_a + sa]      = __float2bfloat16(c00);
                C16[base_a + Sq + sa] = __float2bfloat16(c01);
                C16[base_b + sb]      = __float2bfloat16(c10);
                C16[base_b + Sq + sb] = __float2bfloat16(c11);
            }
        }
    }
}

// ---------------------------------------------------------------------------
// Flash attention, bf16 m16n8k16, register-passed P, cp.async double-buffered
// K/V tiles, B-frags via ldmatrix.x4, exp2-domain softmax (Q pre-scaled by
// 0.125*log2e in the GEMM epilogue).
// smem row = 36 u32 (144 B): data in u32 [0,32).
// ---------------------------------------------------------------------------
__global__ __launch_bounds__(256, 2) void attn_tc_kernel(
    const int* __restrict__ mask,
    const __nv_bfloat16* __restrict__ Q, const __nv_bfloat16* __restrict__ K,
    const __nv_bfloat16* __restrict__ VT, float* __restrict__ O)
{
    __shared__ __align__(16) uint32_t KsP[2][64 * 36];
    __shared__ __align__(16) uint32_t VsP[2][64 * 36];

    const int tid  = threadIdx.x;
    const int w    = tid >> 5;
    const int lane = tid & 31;
    const int g    = lane >> 2;
    const int t    = lane & 3;

    const int qt = blockIdx.x;
    const int h  = blockIdx.y;
    const int b  = blockIdx.z;
    const size_t bh = (size_t)b * Hq + h;
    const __nv_bfloat16* Kb  = K  + bh * Sq * DKq;
    const __nv_bfloat16* VTb = VT + bh * DKq * Sq;

    // Q A-frags straight from bf16 gmem (already scaled by 0.125*log2e)
    uint32_t qa[4][4];
    {
        const uint32_t* Qu0 = (const uint32_t*)
            (Q + (bh * Sq + (size_t)qt * 128 + w * 16 + g) * DKq);
        const uint32_t* Qu1 = Qu0 + 8 * (DKq / 2);
#pragma unroll
        for (int ks = 0; ks < 4; ks++) {
            qa[ks][0] = Qu0[ks * 8 + t];
            qa[ks][1] = Qu1[ks * 8 + t];
            qa[ks][2] = Qu0[ks * 8 + 4 + t];
            qa[ks][3] = Qu1[ks * 8 + 4 + t];
        }
    }

    uint32_t ks_base[2], vs_base[2];
    ks_base[0] = (uint32_t)__cvta_generic_to_shared(&KsP[0][0]);
    ks_base[1] = (uint32_t)__cvta_generic_to_shared(&KsP[1][0]);
    vs_base[0] = (uint32_t)__cvta_generic_to_shared(&VsP[0][0]);
    vs_base[1] = (uint32_t)__cvta_generic_to_shared(&VsP[1][0]);

    // ldmatrix per-lane offset (bytes): matrices = (rows 0-7 kh0, rows 0-7 kh1,
    // rows 8-15 kh0, rows 8-15 kh1) relative to a 16-row block
    const uint32_t lmoff =
        ((((lane >> 4) << 3) + (lane & 7)) * 36 + ((lane >> 3) & 1) * 4) * 4;

    // async copy of one KV tile into buffer `buf`
    auto copyKV = [&](int buf, int kt) {
#pragma unroll
        for (int it = 0; it < 2; it++) {
            int c = tid + it * 256;           // 512 chunks each
            int r = c >> 3, col = c & 7;
            cpa16(ks_base[buf] + (uint32_t)(r * 36 + col * 4) * 4,
                  Kb + (size_t)kt * 64 * DKq + r * DKq + col * 8);
            cpa16(vs_base[buf] + (uint32_t)(r * 36 + col * 4) * 4,
                  VTb + (size_t)r * Sq + kt * 64 + col * 8);
        }
    };

    float o[8][4];
#pragma unroll
    for (int nt = 0; nt < 8; nt++)
#pragma unroll
        for (int j = 0; j < 4; j++) o[nt][j] = 0.f;
    float m0 = -1e30f, m1 = -1e30f, lp0 = 0.f, lp1 = 0.f;

    const int row0 = qt * 128 + w * 16 + g;
    const int2* mrow0 = (const int2*)(mask + ((size_t)b * Sq + row0) * Sq);
    const int2* mrow1 = (const int2*)(mask + ((size_t)b * Sq + row0 + 8) * Sq);

    const int T = Sq / 64;
    copyKV(0, 0);
    asm volatile("cp.async.commit_group;" ::: "memory");

    for (int kt = 0; kt < T; kt++) {
        const int buf = kt & 1;
        __syncthreads();   // all warps done reading buf^1 (iter kt-1)
        if (kt + 1 < T) {
            copyKV(buf ^ 1, kt + 1);
            asm volatile("cp.async.commit_group;" ::: "memory");
            asm volatile("cp.async.wait_group 1;" ::: "memory");
        } else {
            asm volatile("cp.async.wait_group 0;" ::: "memory");
        }
        __syncthreads();   // tile kt visible to all

        const uint32_t kb_s = ks_base[buf] + lmoff;
        const uint32_t vb_s = vs_base[buf] + lmoff;

        // ---- S = Q K^T (warp: 16 x 64), B-frags via ldmatrix.x4
        float cs[8][4];
#pragma unroll
        for (int nt = 0; nt < 8; nt++)
#pragma unroll
            for (int j = 0; j < 4; j++) cs[nt][j] = 0.f;

#pragma unroll
        for (int ks = 0; ks < 4; ks++) {
#pragma unroll
            for (int p = 0; p < 4; p++) {
                uint32_t b0, b1, b2, b3;
                ldsm4(b0, b1, b2, b3, kb_s + (uint32_t)(p * 2304 + ks * 32));
                mma_bf16(cs[2 * p], qa[ks][0], qa[ks][1], qa[ks][2], qa[ks][3],
                         b0, b1);
                mma_bf16(cs[2 * p + 1], qa[ks][0], qa[ks][1], qa[ks][2], qa[ks][3],
                         b2, b3);
            }
        }

        // ---- mask
        const int mbase = kt * 32;
#pragma unroll
        for (int nt = 0; nt < 8; nt++) {
            int2 u0 = mrow0[mbase + nt * 4 + t];
            int2 u1 = mrow1[mbase + nt * 4 + t];
            cs[nt][0] = u0.x ? cs[nt][0] : NEGV;
            cs[nt][1] = u0.y ? cs[nt][1] : NEGV;
            cs[nt][2] = u1.x ? cs[nt][2] : NEGV;
            cs[nt][3] = u1.y ? cs[nt][3] : NEGV;
        }

        // ---- online softmax in exp2 domain (rows g and g+8)
        float mx0 = NEGV, mx1 = NEGV;
#pragma unroll
        for (int nt = 0; nt < 8; nt++) {
            mx0 = fmaxf(mx0, fmaxf(cs[nt][0], cs[nt][1]));
            mx1 = fmaxf(mx1, fmaxf(cs[nt][2], cs[nt][3]));
        }
        mx0 = fmaxf(mx0, __shfl_xor_sync(0xffffffffu, mx0, 1));
        mx0 = fmaxf(mx0, __shfl_xor_sync(0xffffffffu, mx0, 2));
        mx1 = fmaxf(mx1, __shfl_xor_sync(0xffffffffu, mx1, 1));
        mx1 = fmaxf(mx1, __shfl_xor_sync(0xffffffffu, mx1, 2));
        float mn0 = fmaxf(m0, mx0), mn1 = fmaxf(m1, mx1);
        float al0 = ex2(m0 - mn0), al1 = ex2(m1 - mn1);
        m0 = mn0; m1 = mn1;

        uint32_t pA0[8], pA1[8];
        float s0 = 0.f, s1 = 0.f;
#pragma unroll
        for (int nt = 0; nt < 8; nt++) {
            float p00 = ex2(cs[nt][0] - mn0);
            float p01 = ex2(cs[nt][1] - mn0);
            float p10 = ex2(cs[nt][2] - mn1);
            float p11 = ex2(cs[nt][3] - mn1);
            s0 += p00 + p01;
            s1 += p10 + p11;
            pA0[nt] = bf16x2(p00, p01);
            pA1[nt] = bf16x2(p10, p11);
        }
        lp0 = lp0 * al0 + s0;     // cross-t reduction deferred to epilogue
        lp1 = lp1 * al1 + s1;
#pragma unroll
        for (int nt = 0; nt < 8; nt++) {
            o[nt][0] *= al0; o[nt][1] *= al0;
            o[nt][2] *= al1; o[nt][3] *= al1;
        }

        // ---- O += P V  (A = register-passed bf16 P; B via ldmatrix.x4)
#pragma unroll
        for (int j = 0; j < 4; j++) {
            uint32_t a0 = pA0[2 * j];
            uint32_t a1 = pA1[2 * j];
            uint32_t a2 = pA0[2 * j + 1];
            uint32_t a3 = pA1[2 * j + 1];
#pragma unroll
            for (int p = 0; p < 4; p++) {
                uint32_t b0, b1, b2, b3;
                ldsm4(b0, b1, b2, b3, vb_s + (uint32_t)(p * 2304 + j * 32));
                mma_bf16(o[2 * p], a0, a1, a2, a3, b0, b1);
                mma_bf16(o[2 * p + 1], a0, a1, a2, a3, b2, b3);
            }
        }
    }

    // ---- epilogue: reduce partial l across the 4 t-lanes, then write
    lp0 += __shfl_xor_sync(0xffffffffu, lp0, 1);
    lp0 += __shfl_xor_sync(0xffffffffu, lp0, 2);
    lp1 += __shfl_xor_sync(0xffffffffu, lp1, 1);
    lp1 += __shfl_xor_sync(0xffffffffu, lp1, 2);
    const float inv0 = 1.0f / lp0, inv1 = 1.0f / lp1;
    float* op0 = O + ((size_t)b * Sq + row0) * Dq + h * DKq;
    float* op1 = O + ((size_t)b * Sq + row0 + 8) * Dq + h * DKq;
#pragma unroll
    for (int nt = 0; nt < 8; nt++) {
        *(float2*)&op0[nt * 8 + 2 * t] =
            make_float2(o[nt][0] * inv0, o[nt][1] * inv0);
        *(float2*)&op1[nt * 8 + 2 * t] =
            make_float2(o[nt][2] * inv1, o[nt][3] * inv1);
    }
}

// ---------------------------------------------------------------------------
extern "C" void kernel_launch(void* const* d_in, const int* in_sizes, int n_in,
                              void* d_out, int out_size)
{
    const float* x    = (const float*)d_in[0];
    const int*   mask = (const int*)  d_in[1];
    const float* Wqp  = (const float*)d_in[2];
    const float* bqp  = (const float*)d_in[3];
    const float* Wkp  = (const float*)d_in[4];
    const float* bkp  = (const float*)d_in[5];
    const float* Wvp  = (const float*)d_in[6];
    const float* bvp  = (const float*)d_in[7];
    const float* Wop  = (const float*)d_in[8];
    const float* bop  = (const float*)d_in[9];
    float* out = (float*)d_out;

    __nv_bfloat16 *qb, *kb, *vt;
    float *op;
    cudaGetSymbolAddress((void**)&qb, g_qb);
    cudaGetSymbolAddress((void**)&kb, g_kb);
    cudaGetSymbolAddress((void**)&vt, g_vt);
    cudaGetSymbolAddress((void**)&op, g_o);

    dim3 gg(768 / 128, Mrows / 128);   // (6, 64)

    // Q pre-scaled by 1/sqrt(dk) * log2(e) for exp2-domain softmax
    gemm_tc_kernel<<<gg, 256>>>(x, Wqp, bqp, qb, 1, 0.125f * 1.44269504f);
    gemm_tc_kernel<<<gg, 256>>>(x, Wkp, bkp, kb, 1, 1.0f);
    gemm_tc_kernel<<<gg, 256>>>(x, Wvp, bvp, vt, 2, 1.0f);

    attn_tc_kernel<<<dim3(Sq / 128, Hq, Bq), 256>>>(mask, qb, kb, vt, op);

    gemm_tc_kernel<<<gg, 256>>>(op, Wop, bop, out, 0, 1.0f);
}